// round 10
// baseline (speedup 1.0000x reference)
#include <cuda_runtime.h>
#include <cuda_bf16.h>
#include <cstdint>
#include <math.h>

#define I_ 64
#define R_ 36
#define D_ 1024
#define C_ 64
#define W_ 32
#define N_ (I_*R_)       // 2304
#define MROWS (C_*W_)    // 2048
#define SMOOTH_ 9.0f
#define EPS_ 1e-8f
#define MASK_VAL_ (-1.0f)

// GEMM tiling (BM=64 for wave balance)
#define BM 64
#define BN 128
#define BK 32
#define NSTAGE (D_/BK)           // 32
#define ROWB 80
#define TA (BM*ROWB)             // 5120
#define TB (BN*ROWB)             // 10240
#define STGB (2*TA + 2*TB)       // 30720
#define GEMM_SMEM (2*STGB)       // 61440
#define MB2 (MROWS/BM)           // 32
#define NB2 (N_/BN)              // 18

// Gram k-split
#define GCH 8
#define GSZ (I_*R_*R_)           // 82944

// mega-kernel partition
#define ACH (MROWS * (D_/8))     // 262144
#define BCH (N_ * (D_/8))        // 294912
#define CONVB ((ACH + BCH) / 256) // 2176
#define GRAMB (I_ * GCH)          // 512
#define CAPNB C_                  // 64
#define MEGAB (CONVB + GRAMB + CAPNB)

// ---- static scratch ----
__device__ float d_S[MROWS * N_];
__device__ float d_G[GSZ];
__device__ float d_Gp[GCH][GSZ];
__device__ float d_capn[C_ * W_];
__device__ int   d_rowmap[MROWS];
__device__ int   d_actoff[C_];
__device__ int   d_act_total;

__device__ __nv_bfloat16 d_Ath[MROWS * D_];
__device__ __nv_bfloat16 d_Atl[MROWS * D_];
__device__ __nv_bfloat16 d_Bth[N_ * D_];
__device__ __nv_bfloat16 d_Btl[N_ * D_];

// ================= PTX helpers =================
__device__ __forceinline__ uint32_t smem_u32(const void* p) {
    uint32_t a;
    asm("{ .reg .u64 t; cvta.to.shared.u64 t, %1; cvt.u32.u64 %0, t; }" : "=r"(a) : "l"(p));
    return a;
}
__device__ __forceinline__ void cpasync16(uint32_t dst, const void* src) {
    asm volatile("cp.async.cg.shared.global [%0], [%1], 16;" :: "r"(dst), "l"(src) : "memory");
}
#define CP_COMMIT() asm volatile("cp.async.commit_group;" ::: "memory")
#define CP_WAIT(n)  asm volatile("cp.async.wait_group %0;" :: "n"(n) : "memory")

__device__ __forceinline__ void ldsm4(uint32_t r[4], uint32_t addr) {
    asm volatile("ldmatrix.sync.aligned.m8n8.x4.shared.b16 {%0,%1,%2,%3}, [%4];"
                 : "=r"(r[0]), "=r"(r[1]), "=r"(r[2]), "=r"(r[3]) : "r"(addr));
}
__device__ __forceinline__ void mma16816(float* d, const uint32_t* a, const uint32_t* b0, const uint32_t* b1) {
    asm volatile("mma.sync.aligned.m16n8k16.row.col.f32.bf16.bf16.f32 "
                 "{%0,%1,%2,%3},{%4,%5,%6,%7},{%8,%9},{%0,%1,%2,%3};"
                 : "+f"(d[0]), "+f"(d[1]), "+f"(d[2]), "+f"(d[3])
                 : "r"(a[0]), "r"(a[1]), "r"(a[2]), "r"(a[3]), "r"(*b0), "r"(*b1));
}

// ============================================================
// 0) compaction of active (c,w) rows
// ============================================================
__global__ void prep_kernel(const int* __restrict__ cap_lens) {
    __shared__ int offs[C_ + 1];
    int tid = threadIdx.x;
    if (tid == 0) {
        int run = 0;
        for (int c = 0; c < C_; c++) { offs[c] = run; run += cap_lens[c]; }
        offs[C_] = run;
        d_act_total = run;
    }
    __syncthreads();
    int c = tid;
    int off = offs[c], nw = cap_lens[c];
    d_actoff[c] = off;
    for (int w = 0; w < nw; w++) d_rowmap[off + w] = c * W_ + w;
    int total = offs[C_];
    for (int idx = total + tid; idx < MROWS; idx += C_) d_rowmap[idx] = 0;
}

// ============================================================
// mega kernel: convert + gram + capn
// ============================================================
__device__ __forceinline__ void do_convert(int t, const float* __restrict__ caps,
                                           const float* __restrict__ imgs) {
    const float* src;
    size_t dsto;
    __nv_bfloat16 *bh, *bl;
    if (t < ACH) {
        int row = t >> 7, c8 = t & 127;
        src = caps + (size_t)d_rowmap[row] * D_ + c8 * 8;
        dsto = (size_t)row * D_ + c8 * 8;
        bh = d_Ath; bl = d_Atl;
    } else {
        int u = t - ACH;
        int row = u >> 7, c8 = u & 127;
        src = imgs + (size_t)row * D_ + c8 * 8;
        dsto = (size_t)row * D_ + c8 * 8;
        bh = d_Bth; bl = d_Btl;
    }
    float4 v0 = *reinterpret_cast<const float4*>(src);
    float4 v1 = *reinterpret_cast<const float4*>(src + 4);
    float v[8] = {v0.x, v0.y, v0.z, v0.w, v1.x, v1.y, v1.z, v1.w};
    union { __nv_bfloat16 h[8]; uint4 u; } Hi, Lo;
    #pragma unroll
    for (int k = 0; k < 8; k++) {
        __nv_bfloat16 hb = __float2bfloat16(v[k]);
        float r = v[k] - __bfloat162float(hb);
        Hi.h[k] = hb;
        Lo.h[k] = __float2bfloat16(r);
    }
    *reinterpret_cast<uint4*>(bh + dsto) = Hi.u;
    *reinterpret_cast<uint4*>(bl + dsto) = Lo.u;
}

__global__ void __launch_bounds__(256) mega_kernel(const float* __restrict__ caps,
                                                   const float* __restrict__ imgs) {
    __shared__ float sm[R_][132];
    int b = blockIdx.x, tid = threadIdx.x;

    if (b < CONVB) {
        do_convert(b * 256 + tid, caps, imgs);
        return;
    }
    if (b < CONVB + GRAMB) {
        int gb = b - CONVB;
        int i = gb >> 3, ch = gb & 7;
        const float* base = imgs + (size_t)i * R_ * D_ + ch * 128;
        for (int idx = tid; idx < R_ * 32; idx += 256) {
            int r = idx >> 5, d4 = idx & 31;
            float4 v = *reinterpret_cast<const float4*>(base + r * D_ + d4 * 4);
            *reinterpret_cast<float4*>(&sm[r][d4 * 4]) = v;
        }
        __syncthreads();
        if (tid < 144) {
            int tr = tid / 12, tc = tid % 12;
            float acc[3][3] = {};
            #pragma unroll 2
            for (int d = 0; d < 128; d += 4) {
                float4 A0 = *reinterpret_cast<const float4*>(&sm[tr*3+0][d]);
                float4 A1 = *reinterpret_cast<const float4*>(&sm[tr*3+1][d]);
                float4 A2 = *reinterpret_cast<const float4*>(&sm[tr*3+2][d]);
                float4 B0 = *reinterpret_cast<const float4*>(&sm[tc*3+0][d]);
                float4 B1 = *reinterpret_cast<const float4*>(&sm[tc*3+1][d]);
                float4 B2 = *reinterpret_cast<const float4*>(&sm[tc*3+2][d]);
                acc[0][0] = fmaf(A0.x,B0.x,fmaf(A0.y,B0.y,fmaf(A0.z,B0.z,fmaf(A0.w,B0.w,acc[0][0]))));
                acc[0][1] = fmaf(A0.x,B1.x,fmaf(A0.y,B1.y,fmaf(A0.z,B1.z,fmaf(A0.w,B1.w,acc[0][1]))));
                acc[0][2] = fmaf(A0.x,B2.x,fmaf(A0.y,B2.y,fmaf(A0.z,B2.z,fmaf(A0.w,B2.w,acc[0][2]))));
                acc[1][0] = fmaf(A1.x,B0.x,fmaf(A1.y,B0.y,fmaf(A1.z,B0.z,fmaf(A1.w,B0.w,acc[1][0]))));
                acc[1][1] = fmaf(A1.x,B1.x,fmaf(A1.y,B1.y,fmaf(A1.z,B1.z,fmaf(A1.w,B1.w,acc[1][1]))));
                acc[1][2] = fmaf(A1.x,B2.x,fmaf(A1.y,B2.y,fmaf(A1.z,B2.z,fmaf(A1.w,B2.w,acc[1][2]))));
                acc[2][0] = fmaf(A2.x,B0.x,fmaf(A2.y,B0.y,fmaf(A2.z,B0.z,fmaf(A2.w,B0.w,acc[2][0]))));
                acc[2][1] = fmaf(A2.x,B1.x,fmaf(A2.y,B1.y,fmaf(A2.z,B1.z,fmaf(A2.w,B1.w,acc[2][1]))));
                acc[2][2] = fmaf(A2.x,B2.x,fmaf(A2.y,B2.y,fmaf(A2.z,B2.z,fmaf(A2.w,B2.w,acc[2][2]))));
            }
            float* dst = d_Gp[ch] + i * (R_*R_);
            #pragma unroll
            for (int a = 0; a < 3; a++)
                #pragma unroll
                for (int bb = 0; bb < 3; bb++)
                    dst[(tr*3+a) * R_ + (tc*3+bb)] = acc[a][bb];
        }
        return;
    }
    // capn
    {
        int c = b - (CONVB + GRAMB);
        int w = tid >> 3, l = tid & 7;
        const float* p = caps + ((size_t)(c * W_ + w)) * D_;
        float s = 0.f;
        for (int d = l; d < D_; d += 8) { float v = p[d]; s += v * v; }
        s += __shfl_down_sync(0xffffffffu, s, 4);
        s += __shfl_down_sync(0xffffffffu, s, 2);
        s += __shfl_down_sync(0xffffffffu, s, 1);
        if (l == 0) d_capn[c * W_ + w] = s;
    }
}

// ============================================================
// HMMA bf16x3 GEMM (BM=64, 2 CTAs/SM) + fused gram reduce row
// ============================================================
__global__ void __launch_bounds__(256, 2) gemm_mma_kernel() {
    extern __shared__ __align__(128) char smc[];
    int tid = threadIdx.x;

    if (blockIdx.y == MB2) {
        for (int t = blockIdx.x * 256 + tid; t < GSZ; t += NB2 * 256) {
            float s = 0.f;
            #pragma unroll
            for (int p = 0; p < GCH; p++) s += d_Gp[p][t];
            d_G[t] = s;
        }
        return;
    }

    uint32_t sb = smem_u32(smc);
    int wid = tid >> 5, lane = tid & 31;

    int act = d_act_total;
    int mblk = blockIdx.y;
    if (mblk * BM >= act) return;
    int nblk = blockIdx.x;

    int wr = wid & 1, wc = wid >> 1;

    const __nv_bfloat16* srcA[2] = {
        d_Ath + (size_t)mblk * BM * D_,
        d_Atl + (size_t)mblk * BM * D_
    };
    const __nv_bfloat16* srcB[2] = {
        d_Bth + (size_t)nblk * BN * D_,
        d_Btl + (size_t)nblk * BN * D_
    };

    int q = lane >> 3, lr = lane & 7;
    int rowoff = ((q & 1) << 3) + lr;
    int csel = q >> 1;
    uint32_t aoff = (uint32_t)((wr * 32 + rowoff) * ROWB + csel * 16);
    uint32_t boff = (uint32_t)((wc * 32 + rowoff) * ROWB + csel * 16);

    float acc[2][4][4] = {};

    #define LOAD_STAGE(s, k0) do {                                              \
        _Pragma("unroll")                                                        \
        for (int it = 0; it < 6; it++) {                                         \
            int ci = tid + it * 256;                                             \
            const char* g; uint32_t dd;                                          \
            if (ci < 512) {                                                      \
                int tt = ci >> 8, r2 = ci & 255;                                  \
                int row = r2 >> 2, cc = r2 & 3;                                   \
                g = (const char*)(srcA[tt] + (size_t)row * D_ + (k0)) + cc * 16;  \
                dd = sb + (uint32_t)((s) * STGB + tt * TA + row * ROWB + cc * 16);\
            } else {                                                              \
                int u = ci - 512;                                                 \
                int tt = u >> 9, r2 = u & 511;                                    \
                int row = r2 >> 2, cc = r2 & 3;                                   \
                g = (const char*)(srcB[tt] + (size_t)row * D_ + (k0)) + cc * 16;  \
                dd = sb + (uint32_t)((s) * STGB + 2 * TA + tt * TB + row * ROWB + cc * 16); \
            }                                                                     \
            cpasync16(dd, g);                                                     \
        }                                                                         \
        CP_COMMIT();                                                              \
    } while (0)

    LOAD_STAGE(0, 0);

    for (int ks = 0; ks < NSTAGE; ks++) {
        int s = ks & 1;
        if (ks + 1 < NSTAGE) { LOAD_STAGE(s ^ 1, (ks + 1) * BK); CP_WAIT(1); }
        else                 { CP_WAIT(0); }
        __syncthreads();

        uint32_t bAh = sb + (uint32_t)(s * STGB);
        uint32_t bAl = bAh + TA;
        uint32_t bBh = bAh + 2 * TA;
        uint32_t bBl = bBh + TB;

        #pragma unroll
        for (int k16 = 0; k16 < 2; k16++) {
            uint32_t kb = (uint32_t)(k16 * 32);
            uint32_t ah[2][4], al[2][4];
            uint32_t bhf[4][2], blf[4][2];
            #pragma unroll
            for (int mt = 0; mt < 2; mt++) {
                ldsm4(ah[mt], bAh + (uint32_t)(mt * 16 * ROWB) + kb + aoff);
                ldsm4(al[mt], bAl + (uint32_t)(mt * 16 * ROWB) + kb + aoff);
            }
            #pragma unroll
            for (int np = 0; np < 2; np++) {
                uint32_t t4[4];
                ldsm4(t4, bBh + (uint32_t)(np * 16 * ROWB) + kb + boff);
                bhf[np*2+0][0] = t4[0]; bhf[np*2+0][1] = t4[2];
                bhf[np*2+1][0] = t4[1]; bhf[np*2+1][1] = t4[3];
                ldsm4(t4, bBl + (uint32_t)(np * 16 * ROWB) + kb + boff);
                blf[np*2+0][0] = t4[0]; blf[np*2+0][1] = t4[2];
                blf[np*2+1][0] = t4[1]; blf[np*2+1][1] = t4[3];
            }
            #pragma unroll
            for (int mt = 0; mt < 2; mt++)
                #pragma unroll
                for (int nt = 0; nt < 4; nt++) {
                    mma16816(acc[mt][nt], ah[mt], &bhf[nt][0], &bhf[nt][1]);
                    mma16816(acc[mt][nt], ah[mt], &blf[nt][0], &blf[nt][1]);
                    mma16816(acc[mt][nt], al[mt], &bhf[nt][0], &bhf[nt][1]);
                }
        }
        __syncthreads();
    }

    int g = lane >> 2, tq = lane & 3;
    #pragma unroll
    for (int mt = 0; mt < 2; mt++) {
        int m0 = mblk * BM + wr * 32 + mt * 16 + g;
        #pragma unroll
        for (int nt = 0; nt < 4; nt++) {
            int n = nblk * BN + wc * 32 + nt * 8 + tq * 2;
            if (m0 < act)
                *reinterpret_cast<float2*>(d_S + (size_t)m0 * N_ + n) =
                    make_float2(acc[mt][nt][0], acc[mt][nt][1]);
            if (m0 + 8 < act)
                *reinterpret_cast<float2*>(d_S + (size_t)(m0 + 8) * N_ + n) =
                    make_float2(acc[mt][nt][2], acc[mt][nt][3]);
        }
    }
}

// ============================================================
// epilogue: one warp per (c,i), one lane per w.
// |softmax arg| <= SMOOTH (since |l| <= column norm) -> no max pass.
// 4-way ILP accumulators to break serial chains.
// ============================================================
__global__ void __launch_bounds__(256, 3) post_kernel(const int* __restrict__ cap_lens,
                                                      float* __restrict__ out) {
    int i = blockIdx.x, cg = blockIdx.y;
    int tid = threadIdx.x, wid = tid >> 5, lane = tid & 31;
    int c = cg * 8 + wid;

    __shared__ float Gs[R_][R_];          // 36x36, row = 144B
    __shared__ float Ss[8][W_][37];       // per-warp raw S staging
    __shared__ float rcn[8][R_];          // SMOOTH / (sqrt(.)+EPS)

    // cooperative G load (once per 8 c's)
    const float* gG = d_G + i * (R_ * R_);
    for (int idx = tid; idx < R_ * R_; idx += 256)
        Gs[idx / R_][idx % R_] = gG[idx];

    int nw = cap_lens[c], m0 = d_actoff[c];

    // stage this warp's raw S rows: Ss[wid][w][r]
    for (int idx = lane; idx < nw * R_; idx += 32) {
        int w = idx / R_, r = idx - w * R_;
        Ss[wid][w][r] = d_S[(size_t)(m0 + w) * N_ + i * R_ + r];
    }
    __syncwarp();

    // rcn[r] = SMOOTH / (sqrt(sum_w leaky^2) + EPS)  (2-way ILP)
    {
        float s1a = 0.f, s1b = 0.f, s2 = 0.f;
        int w = 0;
        for (; w + 1 < nw; w += 2) {
            float v0 = Ss[wid][w][lane];
            float v1 = Ss[wid][w+1][lane];
            v0 = (v0 >= 0.f) ? v0 : 0.1f * v0;
            v1 = (v1 >= 0.f) ? v1 : 0.1f * v1;
            s1a = fmaf(v0, v0, s1a);
            s1b = fmaf(v1, v1, s1b);
        }
        if (w < nw) {
            float v0 = Ss[wid][w][lane];
            v0 = (v0 >= 0.f) ? v0 : 0.1f * v0;
            s1a = fmaf(v0, v0, s1a);
        }
        if (lane < 4) {
            for (int ww = 0; ww < nw; ww++) {
                float u = Ss[wid][ww][32 + lane];
                u = (u >= 0.f) ? u : 0.1f * u;
                s2 = fmaf(u, u, s2);
            }
        }
        rcn[wid][lane] = SMOOTH_ / (sqrtf(s1a + s1b) + EPS_);
        if (lane < 4) rcn[wid][32 + lane] = SMOOTH_ / (sqrtf(s2) + EPS_);
    }
    __syncthreads();   // Gs ready for everyone; rcn ready per warp

    int w = lane;
    float sim = MASK_VAL_;
    if (w < nw) {
        float a[R_];
        // exp pass: |arg| <= 9, no max shift needed; 4-way partials
        float sum0 = 0.f, sum1 = 0.f, sum2 = 0.f, sum3 = 0.f;
        float sd0 = 0.f, sd1 = 0.f, sd2 = 0.f, sd3 = 0.f;
        #pragma unroll
        for (int r = 0; r < R_; r += 4) {
            float v0 = Ss[wid][w][r+0], v1 = Ss[wid][w][r+1];
            float v2 = Ss[wid][w][r+2], v3 = Ss[wid][w][r+3];
            float l0 = (v0 >= 0.f) ? v0 : 0.1f * v0;
            float l1 = (v1 >= 0.f) ? v1 : 0.1f * v1;
            float l2 = (v2 >= 0.f) ? v2 : 0.1f * v2;
            float l3 = (v3 >= 0.f) ? v3 : 0.1f * v3;
            float e0 = __expf(l0 * rcn[wid][r+0]);
            float e1 = __expf(l1 * rcn[wid][r+1]);
            float e2 = __expf(l2 * rcn[wid][r+2]);
            float e3 = __expf(l3 * rcn[wid][r+3]);
            a[r+0] = e0; a[r+1] = e1; a[r+2] = e2; a[r+3] = e3;
            sum0 += e0; sum1 += e1; sum2 += e2; sum3 += e3;
            sd0 = fmaf(e0, v0, sd0); sd1 = fmaf(e1, v1, sd1);
            sd2 = fmaf(e2, v2, sd2); sd3 = fmaf(e3, v3, sd3);
        }
        float sum = (sum0 + sum1) + (sum2 + sum3);
        float sd  = (sd0 + sd1) + (sd2 + sd3);
        float inv = 1.f / sum;

        // q_e = e^T G e : per row r, 3 independent y-chains of 3 f4 groups
        float qe0 = 0.f, qe1 = 0.f, qe2 = 0.f, qe3 = 0.f;
        #pragma unroll
        for (int r = 0; r < R_; r += 4) {
            #pragma unroll
            for (int rr = 0; rr < 4; rr++) {
                const float4* gr = reinterpret_cast<const float4*>(&Gs[r+rr][0]);
                float y0 = 0.f, y1 = 0.f, y2 = 0.f;
                #pragma unroll
                for (int j = 0; j < 3; j++) {
                    float4 g0 = gr[3*j+0], g1 = gr[3*j+1], g2 = gr[3*j+2];
                    y0 = fmaf(g0.x, a[12*j+0], y0); y0 = fmaf(g0.y, a[12*j+1], y0);
                    y0 = fmaf(g0.z, a[12*j+2], y0); y0 = fmaf(g0.w, a[12*j+3], y0);
                    y1 = fmaf(g1.x, a[12*j+4], y1); y1 = fmaf(g1.y, a[12*j+5], y1);
                    y1 = fmaf(g1.z, a[12*j+6], y1); y1 = fmaf(g1.w, a[12*j+7], y1);
                    y2 = fmaf(g2.x, a[12*j+8], y2); y2 = fmaf(g2.y, a[12*j+9], y2);
                    y2 = fmaf(g2.z, a[12*j+10], y2); y2 = fmaf(g2.w, a[12*j+11], y2);
                }
                float y = (y0 + y1) + y2;
                if (rr == 0) qe0 = fmaf(a[r+rr], y, qe0);
                else if (rr == 1) qe1 = fmaf(a[r+rr], y, qe1);
                else if (rr == 2) qe2 = fmaf(a[r+rr], y, qe2);
                else qe3 = fmaf(a[r+rr], y, qe3);
            }
        }
        float qe = (qe0 + qe1) + (qe2 + qe3);

        float n = sqrtf(qe) * inv;                // ||wctx||
        float dot = sd * inv;                     // cap . wctx
        float denom = n + EPS_;
        float w12 = dot / denom;
        float w2v = n / denom;
        float w1v = sqrtf(d_capn[c * W_ + w]);
        sim = w12 / fmaxf(w1v * w2v, EPS_);
    }
    out[((size_t)i * C_ + c) * W_ + w] = sim;
}

// ============================================================
extern "C" void kernel_launch(void* const* d_in, const int* in_sizes, int n_in,
                              void* d_out, int out_size) {
    const float* imgs     = (const float*)d_in[0];
    const float* caps     = (const float*)d_in[1];
    const int*   cap_lens = (const int*)d_in[3];
    float* out = (float*)d_out;

    cudaFuncSetAttribute(gemm_mma_kernel, cudaFuncAttributeMaxDynamicSharedMemorySize, GEMM_SMEM);

    prep_kernel<<<1, C_>>>(cap_lens);
    mega_kernel<<<MEGAB, 256>>>(caps, imgs);
    dim3 ggrid(NB2, MB2 + 1);   // (18, 33): last y-row = gram reduce
    gemm_mma_kernel<<<ggrid, 256, GEMM_SMEM>>>();
    dim3 pgrid(I_, C_ / 8);
    post_kernel<<<pgrid, 256>>>(cap_lens, out);
}

// round 11
// speedup vs baseline: 1.0359x; 1.0359x over previous
#include <cuda_runtime.h>
#include <cuda_bf16.h>
#include <cstdint>
#include <math.h>

#define I_ 64
#define R_ 36
#define D_ 1024
#define C_ 64
#define W_ 32
#define N_ (I_*R_)       // 2304
#define MROWS (C_*W_)    // 2048
#define SMOOTH_ 9.0f
#define EPS_ 1e-8f
#define MASK_VAL_ (-1.0f)

// GEMM tiling (BM=64 for wave balance)
#define BM 64
#define BN 128
#define BK 32
#define NSTAGE (D_/BK)           // 32
#define ROWB 80
#define TA (BM*ROWB)             // 5120
#define TB (BN*ROWB)             // 10240
#define STGB (2*TA + 2*TB)       // 30720
#define GEMM_SMEM (2*STGB)       // 61440
#define MB2 (MROWS/BM)           // 32
#define NB2 (N_/BN)              // 18

// Gram k-split
#define GCH 8
#define GSZ (I_*R_*R_)           // 82944

// mega-kernel partition
#define ACH (MROWS * (D_/8))     // 262144
#define BCH (N_ * (D_/8))        // 294912
#define CONVB ((ACH + BCH) / 256) // 2176
#define GRAMB (I_ * GCH)          // 512
#define CAPNB C_                  // 64
#define MEGAB (CONVB + GRAMB + CAPNB)

// ---- static scratch ----
__device__ float d_S[MROWS * N_];
__device__ float d_G[GSZ];
__device__ float d_Gp[GCH][GSZ];
__device__ float d_capn[C_ * W_];
__device__ float d_rcn[C_ * I_ * 40];      // SMOOTH/(cn) per (c,i,r)
__device__ int   d_rowmap[MROWS];
__device__ int   d_actoff[C_];
__device__ int   d_act_total;

__device__ __nv_bfloat16 d_Ath[MROWS * D_];
__device__ __nv_bfloat16 d_Atl[MROWS * D_];
__device__ __nv_bfloat16 d_Bth[N_ * D_];
__device__ __nv_bfloat16 d_Btl[N_ * D_];

// ================= PTX helpers =================
__device__ __forceinline__ uint32_t smem_u32(const void* p) {
    uint32_t a;
    asm("{ .reg .u64 t; cvta.to.shared.u64 t, %1; cvt.u32.u64 %0, t; }" : "=r"(a) : "l"(p));
    return a;
}
__device__ __forceinline__ void cpasync16(uint32_t dst, const void* src) {
    asm volatile("cp.async.cg.shared.global [%0], [%1], 16;" :: "r"(dst), "l"(src) : "memory");
}
#define CP_COMMIT() asm volatile("cp.async.commit_group;" ::: "memory")
#define CP_WAIT(n)  asm volatile("cp.async.wait_group %0;" :: "n"(n) : "memory")

__device__ __forceinline__ void ldsm4(uint32_t r[4], uint32_t addr) {
    asm volatile("ldmatrix.sync.aligned.m8n8.x4.shared.b16 {%0,%1,%2,%3}, [%4];"
                 : "=r"(r[0]), "=r"(r[1]), "=r"(r[2]), "=r"(r[3]) : "r"(addr));
}
__device__ __forceinline__ void mma16816(float* d, const uint32_t* a, const uint32_t* b0, const uint32_t* b1) {
    asm volatile("mma.sync.aligned.m16n8k16.row.col.f32.bf16.bf16.f32 "
                 "{%0,%1,%2,%3},{%4,%5,%6,%7},{%8,%9},{%0,%1,%2,%3};"
                 : "+f"(d[0]), "+f"(d[1]), "+f"(d[2]), "+f"(d[3])
                 : "r"(a[0]), "r"(a[1]), "r"(a[2]), "r"(a[3]), "r"(*b0), "r"(*b1));
}

// ============================================================
// 0) compaction of active (c,w) rows
// ============================================================
__global__ void prep_kernel(const int* __restrict__ cap_lens) {
    __shared__ int offs[C_ + 1];
    int tid = threadIdx.x;
    if (tid == 0) {
        int run = 0;
        for (int c = 0; c < C_; c++) { offs[c] = run; run += cap_lens[c]; }
        offs[C_] = run;
        d_act_total = run;
    }
    __syncthreads();
    int c = tid;
    int off = offs[c], nw = cap_lens[c];
    d_actoff[c] = off;
    for (int w = 0; w < nw; w++) d_rowmap[off + w] = c * W_ + w;
    int total = offs[C_];
    for (int idx = total + tid; idx < MROWS; idx += C_) d_rowmap[idx] = 0;
}

// ============================================================
// mega kernel: convert + gram + capn
// ============================================================
__device__ __forceinline__ void do_convert(int t, const float* __restrict__ caps,
                                           const float* __restrict__ imgs) {
    const float* src;
    size_t dsto;
    __nv_bfloat16 *bh, *bl;
    if (t < ACH) {
        int row = t >> 7, c8 = t & 127;
        src = caps + (size_t)d_rowmap[row] * D_ + c8 * 8;
        dsto = (size_t)row * D_ + c8 * 8;
        bh = d_Ath; bl = d_Atl;
    } else {
        int u = t - ACH;
        int row = u >> 7, c8 = u & 127;
        src = imgs + (size_t)row * D_ + c8 * 8;
        dsto = (size_t)row * D_ + c8 * 8;
        bh = d_Bth; bl = d_Btl;
    }
    float4 v0 = *reinterpret_cast<const float4*>(src);
    float4 v1 = *reinterpret_cast<const float4*>(src + 4);
    float v[8] = {v0.x, v0.y, v0.z, v0.w, v1.x, v1.y, v1.z, v1.w};
    union { __nv_bfloat16 h[8]; uint4 u; } Hi, Lo;
    #pragma unroll
    for (int k = 0; k < 8; k++) {
        __nv_bfloat16 hb = __float2bfloat16(v[k]);
        float r = v[k] - __bfloat162float(hb);
        Hi.h[k] = hb;
        Lo.h[k] = __float2bfloat16(r);
    }
    *reinterpret_cast<uint4*>(bh + dsto) = Hi.u;
    *reinterpret_cast<uint4*>(bl + dsto) = Lo.u;
}

__global__ void __launch_bounds__(256) mega_kernel(const float* __restrict__ caps,
                                                   const float* __restrict__ imgs) {
    __shared__ float sm[R_][132];
    int b = blockIdx.x, tid = threadIdx.x;

    if (b < CONVB) {
        do_convert(b * 256 + tid, caps, imgs);
        return;
    }
    if (b < CONVB + GRAMB) {
        int gb = b - CONVB;
        int i = gb >> 3, ch = gb & 7;
        const float* base = imgs + (size_t)i * R_ * D_ + ch * 128;
        for (int idx = tid; idx < R_ * 32; idx += 256) {
            int r = idx >> 5, d4 = idx & 31;
            float4 v = *reinterpret_cast<const float4*>(base + r * D_ + d4 * 4);
            *reinterpret_cast<float4*>(&sm[r][d4 * 4]) = v;
        }
        __syncthreads();
        if (tid < 144) {
            int tr = tid / 12, tc = tid % 12;
            float acc[3][3] = {};
            #pragma unroll 2
            for (int d = 0; d < 128; d += 4) {
                float4 A0 = *reinterpret_cast<const float4*>(&sm[tr*3+0][d]);
                float4 A1 = *reinterpret_cast<const float4*>(&sm[tr*3+1][d]);
                float4 A2 = *reinterpret_cast<const float4*>(&sm[tr*3+2][d]);
                float4 B0 = *reinterpret_cast<const float4*>(&sm[tc*3+0][d]);
                float4 B1 = *reinterpret_cast<const float4*>(&sm[tc*3+1][d]);
                float4 B2 = *reinterpret_cast<const float4*>(&sm[tc*3+2][d]);
                acc[0][0] = fmaf(A0.x,B0.x,fmaf(A0.y,B0.y,fmaf(A0.z,B0.z,fmaf(A0.w,B0.w,acc[0][0]))));
                acc[0][1] = fmaf(A0.x,B1.x,fmaf(A0.y,B1.y,fmaf(A0.z,B1.z,fmaf(A0.w,B1.w,acc[0][1]))));
                acc[0][2] = fmaf(A0.x,B2.x,fmaf(A0.y,B2.y,fmaf(A0.z,B2.z,fmaf(A0.w,B2.w,acc[0][2]))));
                acc[1][0] = fmaf(A1.x,B0.x,fmaf(A1.y,B0.y,fmaf(A1.z,B0.z,fmaf(A1.w,B0.w,acc[1][0]))));
                acc[1][1] = fmaf(A1.x,B1.x,fmaf(A1.y,B1.y,fmaf(A1.z,B1.z,fmaf(A1.w,B1.w,acc[1][1]))));
                acc[1][2] = fmaf(A1.x,B2.x,fmaf(A1.y,B2.y,fmaf(A1.z,B2.z,fmaf(A1.w,B2.w,acc[1][2]))));
                acc[2][0] = fmaf(A2.x,B0.x,fmaf(A2.y,B0.y,fmaf(A2.z,B0.z,fmaf(A2.w,B0.w,acc[2][0]))));
                acc[2][1] = fmaf(A2.x,B1.x,fmaf(A2.y,B1.y,fmaf(A2.z,B1.z,fmaf(A2.w,B1.w,acc[2][1]))));
                acc[2][2] = fmaf(A2.x,B2.x,fmaf(A2.y,B2.y,fmaf(A2.z,B2.z,fmaf(A2.w,B2.w,acc[2][2]))));
            }
            float* dst = d_Gp[ch] + i * (R_*R_);
            #pragma unroll
            for (int a = 0; a < 3; a++)
                #pragma unroll
                for (int bb = 0; bb < 3; bb++)
                    dst[(tr*3+a) * R_ + (tc*3+bb)] = acc[a][bb];
        }
        return;
    }
    // capn
    {
        int c = b - (CONVB + GRAMB);
        int w = tid >> 3, l = tid & 7;
        const float* p = caps + ((size_t)(c * W_ + w)) * D_;
        float s = 0.f;
        for (int d = l; d < D_; d += 8) { float v = p[d]; s += v * v; }
        s += __shfl_down_sync(0xffffffffu, s, 4);
        s += __shfl_down_sync(0xffffffffu, s, 2);
        s += __shfl_down_sync(0xffffffffu, s, 1);
        if (l == 0) d_capn[c * W_ + w] = s;
    }
}

// ============================================================
// HMMA bf16x3 GEMM (BM=64, 2 CTAs/SM) + fused gram reduce row
// ============================================================
__global__ void __launch_bounds__(256, 2) gemm_mma_kernel() {
    extern __shared__ __align__(128) char smc[];
    int tid = threadIdx.x;

    if (blockIdx.y == MB2) {
        for (int t = blockIdx.x * 256 + tid; t < GSZ; t += NB2 * 256) {
            float s = 0.f;
            #pragma unroll
            for (int p = 0; p < GCH; p++) s += d_Gp[p][t];
            d_G[t] = s;
        }
        return;
    }

    uint32_t sb = smem_u32(smc);
    int wid = tid >> 5, lane = tid & 31;

    int act = d_act_total;
    int mblk = blockIdx.y;
    if (mblk * BM >= act) return;
    int nblk = blockIdx.x;

    int wr = wid & 1, wc = wid >> 1;

    const __nv_bfloat16* srcA[2] = {
        d_Ath + (size_t)mblk * BM * D_,
        d_Atl + (size_t)mblk * BM * D_
    };
    const __nv_bfloat16* srcB[2] = {
        d_Bth + (size_t)nblk * BN * D_,
        d_Btl + (size_t)nblk * BN * D_
    };

    int q = lane >> 3, lr = lane & 7;
    int rowoff = ((q & 1) << 3) + lr;
    int csel = q >> 1;
    uint32_t aoff = (uint32_t)((wr * 32 + rowoff) * ROWB + csel * 16);
    uint32_t boff = (uint32_t)((wc * 32 + rowoff) * ROWB + csel * 16);

    float acc[2][4][4] = {};

    #define LOAD_STAGE(s, k0) do {                                              \
        _Pragma("unroll")                                                        \
        for (int it = 0; it < 6; it++) {                                         \
            int ci = tid + it * 256;                                             \
            const char* g; uint32_t dd;                                          \
            if (ci < 512) {                                                      \
                int tt = ci >> 8, r2 = ci & 255;                                  \
                int row = r2 >> 2, cc = r2 & 3;                                   \
                g = (const char*)(srcA[tt] + (size_t)row * D_ + (k0)) + cc * 16;  \
                dd = sb + (uint32_t)((s) * STGB + tt * TA + row * ROWB + cc * 16);\
            } else {                                                              \
                int u = ci - 512;                                                 \
                int tt = u >> 9, r2 = u & 511;                                    \
                int row = r2 >> 2, cc = r2 & 3;                                   \
                g = (const char*)(srcB[tt] + (size_t)row * D_ + (k0)) + cc * 16;  \
                dd = sb + (uint32_t)((s) * STGB + 2 * TA + tt * TB + row * ROWB + cc * 16); \
            }                                                                     \
            cpasync16(dd, g);                                                     \
        }                                                                         \
        CP_COMMIT();                                                              \
    } while (0)

    LOAD_STAGE(0, 0);

    for (int ks = 0; ks < NSTAGE; ks++) {
        int s = ks & 1;
        if (ks + 1 < NSTAGE) { LOAD_STAGE(s ^ 1, (ks + 1) * BK); CP_WAIT(1); }
        else                 { CP_WAIT(0); }
        __syncthreads();

        uint32_t bAh = sb + (uint32_t)(s * STGB);
        uint32_t bAl = bAh + TA;
        uint32_t bBh = bAh + 2 * TA;
        uint32_t bBl = bBh + TB;

        #pragma unroll
        for (int k16 = 0; k16 < 2; k16++) {
            uint32_t kb = (uint32_t)(k16 * 32);
            uint32_t ah[2][4], al[2][4];
            uint32_t bhf[4][2], blf[4][2];
            #pragma unroll
            for (int mt = 0; mt < 2; mt++) {
                ldsm4(ah[mt], bAh + (uint32_t)(mt * 16 * ROWB) + kb + aoff);
                ldsm4(al[mt], bAl + (uint32_t)(mt * 16 * ROWB) + kb + aoff);
            }
            #pragma unroll
            for (int np = 0; np < 2; np++) {
                uint32_t t4[4];
                ldsm4(t4, bBh + (uint32_t)(np * 16 * ROWB) + kb + boff);
                bhf[np*2+0][0] = t4[0]; bhf[np*2+0][1] = t4[2];
                bhf[np*2+1][0] = t4[1]; bhf[np*2+1][1] = t4[3];
                ldsm4(t4, bBl + (uint32_t)(np * 16 * ROWB) + kb + boff);
                blf[np*2+0][0] = t4[0]; blf[np*2+0][1] = t4[2];
                blf[np*2+1][0] = t4[1]; blf[np*2+1][1] = t4[3];
            }
            #pragma unroll
            for (int mt = 0; mt < 2; mt++)
                #pragma unroll
                for (int nt = 0; nt < 4; nt++) {
                    mma16816(acc[mt][nt], ah[mt], &bhf[nt][0], &bhf[nt][1]);
                    mma16816(acc[mt][nt], ah[mt], &blf[nt][0], &blf[nt][1]);
                    mma16816(acc[mt][nt], al[mt], &bhf[nt][0], &bhf[nt][1]);
                }
        }
        __syncthreads();
    }

    int g = lane >> 2, tq = lane & 3;
    #pragma unroll
    for (int mt = 0; mt < 2; mt++) {
        int m0 = mblk * BM + wr * 32 + mt * 16 + g;
        #pragma unroll
        for (int nt = 0; nt < 4; nt++) {
            int n = nblk * BN + wc * 32 + nt * 8 + tq * 2;
            if (m0 < act)
                *reinterpret_cast<float2*>(d_S + (size_t)m0 * N_ + n) =
                    make_float2(acc[mt][nt][0], acc[mt][nt][1]);
            if (m0 + 8 < act)
                *reinterpret_cast<float2*>(d_S + (size_t)(m0 + 8) * N_ + n) =
                    make_float2(acc[mt][nt][2], acc[mt][nt][3]);
        }
    }
}

// ============================================================
// norm kernel: one warp per (c,i). rcn[c][i][r] = SMOOTH/(cn_r);
// also writes the masked (-1) outputs.
// ============================================================
__global__ void __launch_bounds__(256) norm_kernel(const int* __restrict__ cap_lens,
                                                   float* __restrict__ out) {
    int i = blockIdx.x, cg = blockIdx.y;
    int tid = threadIdx.x, wid = tid >> 5, lane = tid & 31;
    int c = cg * 8 + wid;
    int nw = cap_lens[c], m0 = d_actoff[c];

    const float* base = d_S + (size_t)m0 * N_ + i * R_;
    float s1a = 0.f, s1b = 0.f, s2 = 0.f;
    int w = 0;
    for (; w + 1 < nw; w += 2) {
        float v0 = base[(size_t)w * N_ + lane];
        float v1 = base[(size_t)(w+1) * N_ + lane];
        v0 = (v0 >= 0.f) ? v0 : 0.1f * v0;
        v1 = (v1 >= 0.f) ? v1 : 0.1f * v1;
        s1a = fmaf(v0, v0, s1a);
        s1b = fmaf(v1, v1, s1b);
    }
    if (w < nw) {
        float v0 = base[(size_t)w * N_ + lane];
        v0 = (v0 >= 0.f) ? v0 : 0.1f * v0;
        s1a = fmaf(v0, v0, s1a);
    }
    if (lane < 4) {
        for (int ww = 0; ww < nw; ww++) {
            float u = base[(size_t)ww * N_ + 32 + lane];
            u = (u >= 0.f) ? u : 0.1f * u;
            s2 = fmaf(u, u, s2);
        }
    }
    float* rc = d_rcn + ((size_t)c * I_ + i) * 40;
    rc[lane] = SMOOTH_ / (sqrtf(s1a + s1b) + EPS_);
    if (lane < 4) rc[32 + lane] = SMOOTH_ / (sqrtf(s2) + EPS_);
    if (lane >= nw)
        out[((size_t)i * C_ + c) * W_ + lane] = MASK_VAL_;
}

// ============================================================
// post2: one lane per ACTIVE (c,w) row (dense), warp = 32 rows of
// one image. Symmetric 4x4-tile quadratic form: q = qd + 2*qo.
// grid (I_, 8), 256 threads
// ============================================================
__global__ void __launch_bounds__(256, 3) post2_kernel(float* __restrict__ out) {
    int i = blockIdx.x;
    int act = d_act_total;
    int base0 = blockIdx.y * 256;
    if (base0 >= act) return;

    int tid = threadIdx.x, wid = tid >> 5, lane = tid & 31;

    __shared__ float Gs[R_][R_];
    __shared__ float Ss[8][32][37];

    const float* gG = d_G + i * (R_ * R_);
    for (int idx = tid; idx < R_ * R_; idx += 256)
        Gs[idx / R_][idx % R_] = gG[idx];

    int m0w = base0 + wid * 32;
    int nrows = act - m0w;
    if (nrows > 32) nrows = 32;
    if (nrows < 0) nrows = 0;

    for (int idx = lane; idx < nrows * R_; idx += 32) {
        int row = idx / R_, r = idx - row * R_;
        Ss[wid][row][r] = d_S[(size_t)(m0w + row) * N_ + i * R_ + r];
    }
    __syncthreads();

    if (lane < nrows) {
        int rm = d_rowmap[m0w + lane];
        int c = rm >> 5, w = rm & 31;
        const float* rc = d_rcn + ((size_t)c * I_ + i) * 40;

        float a[R_];
        float sum0 = 0.f, sum1 = 0.f, sum2 = 0.f, sum3 = 0.f;
        float sd0 = 0.f, sd1 = 0.f, sd2 = 0.f, sd3 = 0.f;
        #pragma unroll
        for (int r = 0; r < R_; r += 4) {
            float v0 = Ss[wid][lane][r+0], v1 = Ss[wid][lane][r+1];
            float v2 = Ss[wid][lane][r+2], v3 = Ss[wid][lane][r+3];
            float l0 = (v0 >= 0.f) ? v0 : 0.1f * v0;
            float l1 = (v1 >= 0.f) ? v1 : 0.1f * v1;
            float l2 = (v2 >= 0.f) ? v2 : 0.1f * v2;
            float l3 = (v3 >= 0.f) ? v3 : 0.1f * v3;
            float e0 = __expf(l0 * __ldg(rc + r + 0));
            float e1 = __expf(l1 * __ldg(rc + r + 1));
            float e2 = __expf(l2 * __ldg(rc + r + 2));
            float e3 = __expf(l3 * __ldg(rc + r + 3));
            a[r+0] = e0; a[r+1] = e1; a[r+2] = e2; a[r+3] = e3;
            sum0 += e0; sum1 += e1; sum2 += e2; sum3 += e3;
            sd0 = fmaf(e0, v0, sd0); sd1 = fmaf(e1, v1, sd1);
            sd2 = fmaf(e2, v2, sd2); sd3 = fmaf(e3, v3, sd3);
        }
        float sum = (sum0 + sum1) + (sum2 + sum3);
        float sd  = (sd0 + sd1) + (sd2 + sd3);
        float inv = 1.f / sum;

        // symmetric quadratic form over 4x4 tiles: q = qd + 2*qo
        float qd = 0.f, qo0 = 0.f, qo1 = 0.f;
        #pragma unroll
        for (int rg = 0; rg < 9; rg++) {
            // diagonal tile
            #pragma unroll
            for (int aa = 0; aa < 4; aa++) {
                float4 g4 = *reinterpret_cast<const float4*>(&Gs[4*rg+aa][4*rg]);
                float t = g4.x * a[4*rg+0];
                t = fmaf(g4.y, a[4*rg+1], t);
                t = fmaf(g4.z, a[4*rg+2], t);
                t = fmaf(g4.w, a[4*rg+3], t);
                qd = fmaf(a[4*rg+aa], t, qd);
            }
            // off-diagonal tiles (cg > rg)
            #pragma unroll
            for (int cg = rg + 1; cg < 9; cg++) {
                #pragma unroll
                for (int aa = 0; aa < 4; aa++) {
                    float4 g4 = *reinterpret_cast<const float4*>(&Gs[4*rg+aa][4*cg]);
                    float t = g4.x * a[4*cg+0];
                    t = fmaf(g4.y, a[4*cg+1], t);
                    t = fmaf(g4.z, a[4*cg+2], t);
                    t = fmaf(g4.w, a[4*cg+3], t);
                    if ((cg ^ rg) & 1) qo0 = fmaf(a[4*rg+aa], t, qo0);
                    else               qo1 = fmaf(a[4*rg+aa], t, qo1);
                }
            }
        }
        float qe = qd + 2.f * (qo0 + qo1);

        float n = sqrtf(qe) * inv;                // ||wctx||
        float dot = sd * inv;                     // cap . wctx
        float denom = n + EPS_;
        float w12 = dot / denom;
        float w2v = n / denom;
        float w1v = sqrtf(d_capn[rm]);
        float sim = w12 / fmaxf(w1v * w2v, EPS_);
        out[((size_t)i * C_ + c) * W_ + w] = sim;
    }
}

// ============================================================
extern "C" void kernel_launch(void* const* d_in, const int* in_sizes, int n_in,
                              void* d_out, int out_size) {
    const float* imgs     = (const float*)d_in[0];
    const float* caps     = (const float*)d_in[1];
    const int*   cap_lens = (const int*)d_in[3];
    float* out = (float*)d_out;

    cudaFuncSetAttribute(gemm_mma_kernel, cudaFuncAttributeMaxDynamicSharedMemorySize, GEMM_SMEM);

    prep_kernel<<<1, C_>>>(cap_lens);
    mega_kernel<<<MEGAB, 256>>>(caps, imgs);
    dim3 ggrid(NB2, MB2 + 1);   // (18, 33): last y-row = gram reduce
    gemm_mma_kernel<<<ggrid, 256, GEMM_SMEM>>>();
    dim3 ngrid(I_, C_ / 8);
    norm_kernel<<<ngrid, 256>>>(cap_lens, out);
    dim3 pgrid(I_, 8);
    post2_kernel<<<pgrid, 256>>>(out);
}

// round 13
// speedup vs baseline: 1.1021x; 1.0639x over previous
#include <cuda_runtime.h>
#include <cuda_bf16.h>
#include <cstdint>
#include <math.h>

#define I_ 64
#define R_ 36
#define D_ 1024
#define C_ 64
#define W_ 32
#define N_ (I_*R_)       // 2304
#define MROWS (C_*W_)    // 2048
#define SMOOTH_ 9.0f
#define EPS_ 1e-8f
#define MASK_VAL_ (-1.0f)

// GEMM tiling (BM=64 for wave balance)
#define BM 64
#define BN 128
#define BK 32
#define NSTAGE (D_/BK)           // 32
#define ROWB 80
#define TA (BM*ROWB)             // 5120
#define TB (BN*ROWB)             // 10240
#define STGB (2*TA + 2*TB)       // 30720
#define GEMM_SMEM (2*STGB)       // 61440
#define MB2 (MROWS/BM)           // 32
#define NB2 (N_/BN)              // 18

// Gram k-split
#define GCH 8
#define GSZ (I_*R_*R_)           // 82944

// mega-kernel partition
#define ACH (MROWS * (D_/8))     // 262144
#define BCH (N_ * (D_/8))        // 294912
#define CONVB ((ACH + BCH) / 256) // 2176
#define GRAMB (I_ * GCH)          // 512
#define CAPNB C_                  // 64
#define MEGAB (CONVB + GRAMB + CAPNB)

// post2 dynamic smem layout (floats)
#define P2_GS    0                        // [36][36]
#define P2_SS    (P2_GS + R_*R_)          // [8][32][37]
#define P2_RCN   (P2_SS + 8*32*37)        // [64][38]
#define P2_TOTAL (P2_RCN + 64*38)         // floats
#define POST2_SMEM (P2_TOTAL * 4)         // ~53KB

// ---- static scratch ----
__device__ float d_S[MROWS * N_];
__device__ float d_G[GSZ];
__device__ float d_Gp[GCH][GSZ];
__device__ float d_capn[C_ * W_];
__device__ int   d_act_total;

__device__ __nv_bfloat16 d_Ath[MROWS * D_];
__device__ __nv_bfloat16 d_Atl[MROWS * D_];
__device__ __nv_bfloat16 d_Bth[N_ * D_];
__device__ __nv_bfloat16 d_Btl[N_ * D_];

// ================= PTX helpers =================
__device__ __forceinline__ uint32_t smem_u32(const void* p) {
    uint32_t a;
    asm("{ .reg .u64 t; cvta.to.shared.u64 t, %1; cvt.u32.u64 %0, t; }" : "=r"(a) : "l"(p));
    return a;
}
__device__ __forceinline__ void cpasync16(uint32_t dst, const void* src) {
    asm volatile("cp.async.cg.shared.global [%0], [%1], 16;" :: "r"(dst), "l"(src) : "memory");
}
#define CP_COMMIT() asm volatile("cp.async.commit_group;" ::: "memory")
#define CP_WAIT(n)  asm volatile("cp.async.wait_group %0;" :: "n"(n) : "memory")

__device__ __forceinline__ void ldsm4(uint32_t r[4], uint32_t addr) {
    asm volatile("ldmatrix.sync.aligned.m8n8.x4.shared.b16 {%0,%1,%2,%3}, [%4];"
                 : "=r"(r[0]), "=r"(r[1]), "=r"(r[2]), "=r"(r[3]) : "r"(addr));
}
__device__ __forceinline__ void mma16816(float* d, const uint32_t* a, const uint32_t* b0, const uint32_t* b1) {
    asm volatile("mma.sync.aligned.m16n8k16.row.col.f32.bf16.bf16.f32 "
                 "{%0,%1,%2,%3},{%4,%5,%6,%7},{%8,%9},{%0,%1,%2,%3};"
                 : "+f"(d[0]), "+f"(d[1]), "+f"(d[2]), "+f"(d[3])
                 : "r"(a[0]), "r"(a[1]), "r"(a[2]), "r"(a[3]), "r"(*b0), "r"(*b1));
}

// block-local exclusive scan of cap_lens into offs[0..64]
__device__ __forceinline__ void compute_offs(const int* __restrict__ cap_lens,
                                             int* cl, int* offs, int tid) {
    if (tid < C_) cl[tid] = cap_lens[tid];
    __syncthreads();
    if (tid == 0) {
        int run = 0;
        for (int c = 0; c < C_; c++) { offs[c] = run; run += cl[c]; }
        offs[C_] = run;
    }
    __syncthreads();
}
// find c with offs[c] <= row < offs[c+1]
__device__ __forceinline__ int find_c(const int* offs, int row) {
    int lo = 0, hi = C_;
    #pragma unroll
    for (int it = 0; it < 6; it++) {
        int mid = (lo + hi) >> 1;
        if (offs[mid] <= row) lo = mid; else hi = mid;
    }
    return lo;
}

// ============================================================
// mega kernel: convert + gram + capn(+mask+act)
// ============================================================
__global__ void __launch_bounds__(256) mega_kernel(const float* __restrict__ caps,
                                                   const float* __restrict__ imgs,
                                                   const int* __restrict__ cap_lens,
                                                   float* __restrict__ out) {
    __shared__ float sm[R_][132];
    __shared__ int cl[C_], offs[C_ + 1];
    int b = blockIdx.x, tid = threadIdx.x;

    if (b < CONVB) {
        int t = b * 256 + tid;
        const float* src;
        size_t dsto;
        __nv_bfloat16 *bh, *bl;
        if (t < ACH) {
            compute_offs(cap_lens, cl, offs, tid);
            int row = t >> 7, c8 = t & 127;
            int act = offs[C_];
            int srcrow = 0;
            if (row < act) {
                int c = find_c(offs, row);
                srcrow = c * W_ + (row - offs[c]);
            }
            src = caps + (size_t)srcrow * D_ + c8 * 8;
            dsto = (size_t)row * D_ + c8 * 8;
            bh = d_Ath; bl = d_Atl;
        } else {
            int u = t - ACH;
            int row = u >> 7, c8 = u & 127;
            src = imgs + (size_t)row * D_ + c8 * 8;
            dsto = (size_t)row * D_ + c8 * 8;
            bh = d_Bth; bl = d_Btl;
        }
        float4 v0 = *reinterpret_cast<const float4*>(src);
        float4 v1 = *reinterpret_cast<const float4*>(src + 4);
        float v[8] = {v0.x, v0.y, v0.z, v0.w, v1.x, v1.y, v1.z, v1.w};
        union { __nv_bfloat16 h[8]; uint4 u; } Hi, Lo;
        #pragma unroll
        for (int k = 0; k < 8; k++) {
            __nv_bfloat16 hb = __float2bfloat16(v[k]);
            float r = v[k] - __bfloat162float(hb);
            Hi.h[k] = hb;
            Lo.h[k] = __float2bfloat16(r);
        }
        *reinterpret_cast<uint4*>(bh + dsto) = Hi.u;
        *reinterpret_cast<uint4*>(bl + dsto) = Lo.u;
        return;
    }
    if (b < CONVB + GRAMB) {
        int gb = b - CONVB;
        int i = gb >> 3, ch = gb & 7;
        const float* base = imgs + (size_t)i * R_ * D_ + ch * 128;
        for (int idx = tid; idx < R_ * 32; idx += 256) {
            int r = idx >> 5, d4 = idx & 31;
            float4 v = *reinterpret_cast<const float4*>(base + r * D_ + d4 * 4);
            *reinterpret_cast<float4*>(&sm[r][d4 * 4]) = v;
        }
        __syncthreads();
        if (tid < 144) {
            int tr = tid / 12, tc = tid % 12;
            float acc[3][3] = {};
            #pragma unroll 2
            for (int d = 0; d < 128; d += 4) {
                float4 A0 = *reinterpret_cast<const float4*>(&sm[tr*3+0][d]);
                float4 A1 = *reinterpret_cast<const float4*>(&sm[tr*3+1][d]);
                float4 A2 = *reinterpret_cast<const float4*>(&sm[tr*3+2][d]);
                float4 B0 = *reinterpret_cast<const float4*>(&sm[tc*3+0][d]);
                float4 B1 = *reinterpret_cast<const float4*>(&sm[tc*3+1][d]);
                float4 B2 = *reinterpret_cast<const float4*>(&sm[tc*3+2][d]);
                acc[0][0] = fmaf(A0.x,B0.x,fmaf(A0.y,B0.y,fmaf(A0.z,B0.z,fmaf(A0.w,B0.w,acc[0][0]))));
                acc[0][1] = fmaf(A0.x,B1.x,fmaf(A0.y,B1.y,fmaf(A0.z,B1.z,fmaf(A0.w,B1.w,acc[0][1]))));
                acc[0][2] = fmaf(A0.x,B2.x,fmaf(A0.y,B2.y,fmaf(A0.z,B2.z,fmaf(A0.w,B2.w,acc[0][2]))));
                acc[1][0] = fmaf(A1.x,B0.x,fmaf(A1.y,B0.y,fmaf(A1.z,B0.z,fmaf(A1.w,B0.w,acc[1][0]))));
                acc[1][1] = fmaf(A1.x,B1.x,fmaf(A1.y,B1.y,fmaf(A1.z,B1.z,fmaf(A1.w,B1.w,acc[1][1]))));
                acc[1][2] = fmaf(A1.x,B2.x,fmaf(A1.y,B2.y,fmaf(A1.z,B2.z,fmaf(A1.w,B2.w,acc[1][2]))));
                acc[2][0] = fmaf(A2.x,B0.x,fmaf(A2.y,B0.y,fmaf(A2.z,B0.z,fmaf(A2.w,B0.w,acc[2][0]))));
                acc[2][1] = fmaf(A2.x,B1.x,fmaf(A2.y,B1.y,fmaf(A2.z,B1.z,fmaf(A2.w,B1.w,acc[2][1]))));
                acc[2][2] = fmaf(A2.x,B2.x,fmaf(A2.y,B2.y,fmaf(A2.z,B2.z,fmaf(A2.w,B2.w,acc[2][2]))));
            }
            float* dst = d_Gp[ch] + i * (R_*R_);
            #pragma unroll
            for (int a = 0; a < 3; a++)
                #pragma unroll
                for (int bb = 0; bb < 3; bb++)
                    dst[(tr*3+a) * R_ + (tc*3+bb)] = acc[a][bb];
        }
        return;
    }
    // capn + masked outputs + act total
    {
        int c = b - (CONVB + GRAMB);
        int w = tid >> 3, l = tid & 7;
        const float* p = caps + ((size_t)(c * W_ + w)) * D_;
        float s = 0.f;
        for (int d = l; d < D_; d += 8) { float v = p[d]; s += v * v; }
        s += __shfl_down_sync(0xffffffffu, s, 4);
        s += __shfl_down_sync(0xffffffffu, s, 2);
        s += __shfl_down_sync(0xffffffffu, s, 1);
        if (l == 0) d_capn[c * W_ + w] = s;

        if (c == 0 && tid == 0) {
            int run = 0;
            for (int j = 0; j < C_; j++) run += cap_lens[j];
            d_act_total = run;
        }
        int nw = cap_lens[c];
        for (int idx = tid; idx < I_ * W_; idx += 256) {
            int i = idx >> 5, ww = idx & 31;
            if (ww >= nw)
                out[((size_t)i * C_ + c) * W_ + ww] = MASK_VAL_;
        }
    }
}

// ============================================================
// HMMA bf16x3 GEMM (BM=64, 2 CTAs/SM) + fused gram reduce row
// ============================================================
__global__ void __launch_bounds__(256, 2) gemm_mma_kernel() {
    extern __shared__ __align__(128) char smc[];
    int tid = threadIdx.x;

    if (blockIdx.y == MB2) {
        for (int t = blockIdx.x * 256 + tid; t < GSZ; t += NB2 * 256) {
            float s = 0.f;
            #pragma unroll
            for (int p = 0; p < GCH; p++) s += d_Gp[p][t];
            d_G[t] = s;
        }
        return;
    }

    uint32_t sb = smem_u32(smc);
    int wid = tid >> 5, lane = tid & 31;

    int act = d_act_total;
    int mblk = blockIdx.y;
    if (mblk * BM >= act) return;
    int nblk = blockIdx.x;

    int wr = wid & 1, wc = wid >> 1;

    const __nv_bfloat16* srcA[2] = {
        d_Ath + (size_t)mblk * BM * D_,
        d_Atl + (size_t)mblk * BM * D_
    };
    const __nv_bfloat16* srcB[2] = {
        d_Bth + (size_t)nblk * BN * D_,
        d_Btl + (size_t)nblk * BN * D_
    };

    int q = lane >> 3, lr = lane & 7;
    int rowoff = ((q & 1) << 3) + lr;
    int csel = q >> 1;
    uint32_t aoff = (uint32_t)((wr * 32 + rowoff) * ROWB + csel * 16);
    uint32_t boff = (uint32_t)((wc * 32 + rowoff) * ROWB + csel * 16);

    float acc[2][4][4] = {};

    #define LOAD_STAGE(s, k0) do {                                              \
        _Pragma("unroll")                                                        \
        for (int it = 0; it < 6; it++) {                                         \
            int ci = tid + it * 256;                                             \
            const char* g; uint32_t dd;                                          \
            if (ci < 512) {                                                      \
                int tt = ci >> 8, r2 = ci & 255;                                  \
                int row = r2 >> 2, cc = r2 & 3;                                   \
                g = (const char*)(srcA[tt] + (size_t)row * D_ + (k0)) + cc * 16;  \
                dd = sb + (uint32_t)((s) * STGB + tt * TA + row * ROWB + cc * 16);\
            } else {                                                              \
                int u = ci - 512;                                                 \
                int tt = u >> 9, r2 = u & 511;                                    \
                int row = r2 >> 2, cc = r2 & 3;                                   \
                g = (const char*)(srcB[tt] + (size_t)row * D_ + (k0)) + cc * 16;  \
                dd = sb + (uint32_t)((s) * STGB + 2 * TA + tt * TB + row * ROWB + cc * 16); \
            }                                                                     \
            cpasync16(dd, g);                                                     \
        }                                                                         \
        CP_COMMIT();                                                              \
    } while (0)

    LOAD_STAGE(0, 0);

    for (int ks = 0; ks < NSTAGE; ks++) {
        int s = ks & 1;
        if (ks + 1 < NSTAGE) { LOAD_STAGE(s ^ 1, (ks + 1) * BK); CP_WAIT(1); }
        else                 { CP_WAIT(0); }
        __syncthreads();

        uint32_t bAh = sb + (uint32_t)(s * STGB);
        uint32_t bAl = bAh + TA;
        uint32_t bBh = bAh + 2 * TA;
        uint32_t bBl = bBh + TB;

        #pragma unroll
        for (int k16 = 0; k16 < 2; k16++) {
            uint32_t kb = (uint32_t)(k16 * 32);
            uint32_t ah[2][4], al[2][4];
            uint32_t bhf[4][2], blf[4][2];
            #pragma unroll
            for (int mt = 0; mt < 2; mt++) {
                ldsm4(ah[mt], bAh + (uint32_t)(mt * 16 * ROWB) + kb + aoff);
                ldsm4(al[mt], bAl + (uint32_t)(mt * 16 * ROWB) + kb + aoff);
            }
            #pragma unroll
            for (int np = 0; np < 2; np++) {
                uint32_t t4[4];
                ldsm4(t4, bBh + (uint32_t)(np * 16 * ROWB) + kb + boff);
                bhf[np*2+0][0] = t4[0]; bhf[np*2+0][1] = t4[2];
                bhf[np*2+1][0] = t4[1]; bhf[np*2+1][1] = t4[3];
                ldsm4(t4, bBl + (uint32_t)(np * 16 * ROWB) + kb + boff);
                blf[np*2+0][0] = t4[0]; blf[np*2+0][1] = t4[2];
                blf[np*2+1][0] = t4[1]; blf[np*2+1][1] = t4[3];
            }
            #pragma unroll
            for (int mt = 0; mt < 2; mt++)
                #pragma unroll
                for (int nt = 0; nt < 4; nt++) {
                    mma16816(acc[mt][nt], ah[mt], &bhf[nt][0], &bhf[nt][1]);
                    mma16816(acc[mt][nt], ah[mt], &blf[nt][0], &blf[nt][1]);
                    mma16816(acc[mt][nt], al[mt], &bhf[nt][0], &bhf[nt][1]);
                }
        }
        __syncthreads();
    }

    int g = lane >> 2, tq = lane & 3;
    #pragma unroll
    for (int mt = 0; mt < 2; mt++) {
        int m0 = mblk * BM + wr * 32 + mt * 16 + g;
        #pragma unroll
        for (int nt = 0; nt < 4; nt++) {
            int n = nblk * BN + wc * 32 + nt * 8 + tq * 2;
            if (m0 < act)
                *reinterpret_cast<float2*>(d_S + (size_t)m0 * N_ + n) =
                    make_float2(acc[mt][nt][0], acc[mt][nt][1]);
            if (m0 + 8 < act)
                *reinterpret_cast<float2*>(d_S + (size_t)(m0 + 8) * N_ + n) =
                    make_float2(acc[mt][nt][2], acc[mt][nt][3]);
        }
    }
}

// ============================================================
// post2: fused norms + softmax + symmetric quadratic form.
// block = (image i, 256 consecutive active rows); lane per row.
// dynamic smem: Gs | Ss | rcn (rcn sized for 64 c's: cap_lens >= 4)
// ============================================================
__global__ void __launch_bounds__(256, 3) post2_kernel(const int* __restrict__ cap_lens,
                                                       float* __restrict__ out) {
    extern __shared__ float dyn[];
    float* Gs  = dyn + P2_GS;            // [36][36]
    float* Ss  = dyn + P2_SS;            // [8][32][37] flat
    float* rcn = dyn + P2_RCN;           // [64][38]
    __shared__ int cl[C_], offs[C_ + 1];

    int i = blockIdx.x;
    int tid = threadIdx.x, wid = tid >> 5, lane = tid & 31;

    compute_offs(cap_lens, cl, offs, tid);
    int act = offs[C_];
    int base0 = blockIdx.y * 256;
    if (base0 >= act) return;

    const float* gG = d_G + i * (R_ * R_);
    for (int idx = tid; idx < R_ * R_; idx += 256)
        Gs[idx] = gG[idx];

    int blk_rows = act - base0;
    if (blk_rows > 256) blk_rows = 256;

    // stage S rows (warp per 32 rows); Ss[wid][row][r] = Ss[(wid*32+row)*37 + r]
    {
        int m0w = base0 + wid * 32;
        int nrows = act - m0w;
        if (nrows > 32) nrows = 32;
        if (nrows < 0) nrows = 0;
        for (int idx = lane; idx < nrows * R_; idx += 32) {
            int row = idx / R_, r = idx - row * R_;
            Ss[(wid * 32 + row) * 37 + r] = d_S[(size_t)(m0w + row) * N_ + i * R_ + r];
        }
    }
    __syncthreads();

    // fused norms: rcn for all c's overlapping this block's rows
    int c_lo = find_c(offs, base0);
    int c_hi = find_c(offs, base0 + blk_rows - 1);
    int ncs = c_hi - c_lo + 1;           // <= 64 (cap_lens >= 4 -> <= 64 c's/256 rows)
    for (int item = tid; item < ncs * R_; item += 256) {
        int ci = item / R_, r = item - ci * R_;
        int c = c_lo + ci;
        int o = offs[c], nw2 = offs[c + 1] - o;
        float s = 0.f;
        for (int w = 0; w < nw2; w++) {
            int row = o + w;
            int lr2 = row - base0;
            float v = (lr2 >= 0 && lr2 < 256) ? Ss[lr2 * 37 + r]
                                              : d_S[(size_t)row * N_ + i * R_ + r];
            v = (v >= 0.f) ? v : 0.1f * v;
            s = fmaf(v, v, s);
        }
        rcn[ci * 38 + r] = SMOOTH_ / (sqrtf(s) + EPS_);
    }
    __syncthreads();

    int myrow = base0 + wid * 32 + lane;
    if (myrow < act && (wid * 32 + lane) < blk_rows) {
        int c = find_c(offs, myrow);
        int w = myrow - offs[c];
        const float* rc = rcn + (c - c_lo) * 38;
        const float* sr = Ss + (wid * 32 + lane) * 37;

        float a[R_];
        float sum0 = 0.f, sum1 = 0.f, sum2 = 0.f, sum3 = 0.f;
        float sd0 = 0.f, sd1 = 0.f, sd2 = 0.f, sd3 = 0.f;
        #pragma unroll
        for (int r = 0; r < R_; r += 4) {
            float v0 = sr[r+0], v1 = sr[r+1];
            float v2 = sr[r+2], v3 = sr[r+3];
            float l0 = (v0 >= 0.f) ? v0 : 0.1f * v0;
            float l1 = (v1 >= 0.f) ? v1 : 0.1f * v1;
            float l2 = (v2 >= 0.f) ? v2 : 0.1f * v2;
            float l3 = (v3 >= 0.f) ? v3 : 0.1f * v3;
            float e0 = __expf(l0 * rc[r+0]);
            float e1 = __expf(l1 * rc[r+1]);
            float e2 = __expf(l2 * rc[r+2]);
            float e3 = __expf(l3 * rc[r+3]);
            a[r+0] = e0; a[r+1] = e1; a[r+2] = e2; a[r+3] = e3;
            sum0 += e0; sum1 += e1; sum2 += e2; sum3 += e3;
            sd0 = fmaf(e0, v0, sd0); sd1 = fmaf(e1, v1, sd1);
            sd2 = fmaf(e2, v2, sd2); sd3 = fmaf(e3, v3, sd3);
        }
        float sum = (sum0 + sum1) + (sum2 + sum3);
        float sd  = (sd0 + sd1) + (sd2 + sd3);
        float inv = 1.f / sum;

        // symmetric quadratic form over 4x4 tiles: q = qd + 2*qo
        float qd = 0.f, qo0 = 0.f, qo1 = 0.f;
        #pragma unroll
        for (int rg = 0; rg < 9; rg++) {
            #pragma unroll
            for (int aa = 0; aa < 4; aa++) {
                float4 g4 = *reinterpret_cast<const float4*>(&Gs[(4*rg+aa) * R_ + 4*rg]);
                float t = g4.x * a[4*rg+0];
                t = fmaf(g4.y, a[4*rg+1], t);
                t = fmaf(g4.z, a[4*rg+2], t);
                t = fmaf(g4.w, a[4*rg+3], t);
                qd = fmaf(a[4*rg+aa], t, qd);
            }
            #pragma unroll
            for (int cg = rg + 1; cg < 9; cg++) {
                #pragma unroll
                for (int aa = 0; aa < 4; aa++) {
                    float4 g4 = *reinterpret_cast<const float4*>(&Gs[(4*rg+aa) * R_ + 4*cg]);
                    float t = g4.x * a[4*cg+0];
                    t = fmaf(g4.y, a[4*cg+1], t);
                    t = fmaf(g4.z, a[4*cg+2], t);
                    t = fmaf(g4.w, a[4*cg+3], t);
                    if ((cg ^ rg) & 1) qo0 = fmaf(a[4*rg+aa], t, qo0);
                    else               qo1 = fmaf(a[4*rg+aa], t, qo1);
                }
            }
        }
        float qe = qd + 2.f * (qo0 + qo1);

        float n = sqrtf(qe) * inv;
        float dot = sd * inv;
        float denom = n + EPS_;
        float w12 = dot / denom;
        float w2v = n / denom;
        float w1v = sqrtf(d_capn[c * W_ + w]);
        float sim = w12 / fmaxf(w1v * w2v, EPS_);
        out[((size_t)i * C_ + c) * W_ + w] = sim;
    }
}

// ============================================================
extern "C" void kernel_launch(void* const* d_in, const int* in_sizes, int n_in,
                              void* d_out, int out_size) {
    const float* imgs     = (const float*)d_in[0];
    const float* caps     = (const float*)d_in[1];
    const int*   cap_lens = (const int*)d_in[3];
    float* out = (float*)d_out;

    cudaFuncSetAttribute(gemm_mma_kernel, cudaFuncAttributeMaxDynamicSharedMemorySize, GEMM_SMEM);
    cudaFuncSetAttribute(post2_kernel, cudaFuncAttributeMaxDynamicSharedMemorySize, POST2_SMEM);

    mega_kernel<<<MEGAB, 256>>>(caps, imgs, cap_lens, out);
    dim3 ggrid(NB2, MB2 + 1);   // (18, 33): last y-row = gram reduce
    gemm_mma_kernel<<<ggrid, 256, GEMM_SMEM>>>();
    dim3 pgrid(I_, 8);
    post2_kernel<<<pgrid, 256, POST2_SMEM>>>(cap_lens, out);
}

// round 14
// speedup vs baseline: 1.1166x; 1.0132x over previous
#include <cuda_runtime.h>
#include <cuda_bf16.h>
#include <cstdint>
#include <math.h>

#define I_ 64
#define R_ 36
#define D_ 1024
#define C_ 64
#define W_ 32
#define N_ (I_*R_)       // 2304
#define MROWS (C_*W_)    // 2048
#define SMOOTH_ 9.0f
#define EPS_ 1e-8f
#define MASK_VAL_ (-1.0f)

// GEMM tiling (BM=64 for wave balance)
#define BM 64
#define BN 128
#define BK 32
#define NSTAGE (D_/BK)           // 32
#define ROWB 80
#define TA (BM*ROWB)             // 5120
#define TB (BN*ROWB)             // 10240
#define STGB (2*TA + 2*TB)       // 30720
#define GEMM_SMEM (2*STGB)       // 61440
#define MB2 (MROWS/BM)           // 32
#define NB2 (N_/BN)              // 18
#define GEMMB (NB2*MB2)          // 576

// Gram k-split
#define GCH 8
#define GSZ (I_*R_*R_)           // 82944
#define GRAMB (I_ * GCH)         // 512

// mega-kernel partition (convert + capn only now)
#define ACH (MROWS * (D_/8))     // 262144
#define BCH (N_ * (D_/8))        // 294912
#define CONVB ((ACH + BCH) / 256) // 2176
#define CAPNB C_                  // 64
#define MEGAB (CONVB + CAPNB)

// post2 dynamic smem layout (floats)
#define P2_GS    0                        // [36][36]
#define P2_SS    (P2_GS + R_*R_)          // [8][32][37]
#define P2_RCN   (P2_SS + 8*32*37)        // [64][38]
#define P2_TOTAL (P2_RCN + 64*38)
#define POST2_SMEM (P2_TOTAL * 4)         // ~53KB

// ---- static scratch ----
__device__ float d_S[MROWS * N_];
__device__ float d_Gp[GCH][GSZ];
__device__ float d_capn[C_ * W_];
__device__ int   d_act_total;

__device__ __nv_bfloat16 d_Ath[MROWS * D_];
__device__ __nv_bfloat16 d_Atl[MROWS * D_];
__device__ __nv_bfloat16 d_Bth[N_ * D_];
__device__ __nv_bfloat16 d_Btl[N_ * D_];

// ================= PTX helpers =================
__device__ __forceinline__ uint32_t smem_u32(const void* p) {
    uint32_t a;
    asm("{ .reg .u64 t; cvta.to.shared.u64 t, %1; cvt.u32.u64 %0, t; }" : "=r"(a) : "l"(p));
    return a;
}
__device__ __forceinline__ void cpasync16(uint32_t dst, const void* src) {
    asm volatile("cp.async.cg.shared.global [%0], [%1], 16;" :: "r"(dst), "l"(src) : "memory");
}
#define CP_COMMIT() asm volatile("cp.async.commit_group;" ::: "memory")
#define CP_WAIT(n)  asm volatile("cp.async.wait_group %0;" :: "n"(n) : "memory")

__device__ __forceinline__ void ldsm4(uint32_t r[4], uint32_t addr) {
    asm volatile("ldmatrix.sync.aligned.m8n8.x4.shared.b16 {%0,%1,%2,%3}, [%4];"
                 : "=r"(r[0]), "=r"(r[1]), "=r"(r[2]), "=r"(r[3]) : "r"(addr));
}
__device__ __forceinline__ void mma16816(float* d, const uint32_t* a, const uint32_t* b0, const uint32_t* b1) {
    asm volatile("mma.sync.aligned.m16n8k16.row.col.f32.bf16.bf16.f32 "
                 "{%0,%1,%2,%3},{%4,%5,%6,%7},{%8,%9},{%0,%1,%2,%3};"
                 : "+f"(d[0]), "+f"(d[1]), "+f"(d[2]), "+f"(d[3])
                 : "r"(a[0]), "r"(a[1]), "r"(a[2]), "r"(a[3]), "r"(*b0), "r"(*b1));
}

// block-local exclusive scan of cap_lens into offs[0..64] (parallel)
__device__ __forceinline__ void compute_offs(const int* __restrict__ cap_lens,
                                             int* cl, int* offs, int tid) {
    if (tid < C_) cl[tid] = cap_lens[tid];
    __syncthreads();
    if (tid <= C_) {
        int run = 0;
        for (int j = 0; j < tid; j++) run += cl[j];
        offs[tid] = run;
    }
    __syncthreads();
}
// find c with offs[c] <= row < offs[c+1]
__device__ __forceinline__ int find_c(const int* offs, int row) {
    int lo = 0, hi = C_;
    #pragma unroll
    for (int it = 0; it < 6; it++) {
        int mid = (lo + hi) >> 1;
        if (offs[mid] <= row) lo = mid; else hi = mid;
    }
    return lo;
}

// ============================================================
// mega kernel: convert + capn(+mask+act)
// ============================================================
__global__ void __launch_bounds__(256) mega_kernel(const float* __restrict__ caps,
                                                   const float* __restrict__ imgs,
                                                   const int* __restrict__ cap_lens,
                                                   float* __restrict__ out) {
    __shared__ int cl[C_], offs[C_ + 1];
    int b = blockIdx.x, tid = threadIdx.x;

    if (b < CONVB) {
        int t = b * 256 + tid;
        const float* src;
        size_t dsto;
        __nv_bfloat16 *bh, *bl;
        if (t < ACH) {
            compute_offs(cap_lens, cl, offs, tid);
            int row = t >> 7, c8 = t & 127;
            int act = offs[C_];
            int srcrow = 0;
            if (row < act) {
                int c = find_c(offs, row);
                srcrow = c * W_ + (row - offs[c]);
            }
            src = caps + (size_t)srcrow * D_ + c8 * 8;
            dsto = (size_t)row * D_ + c8 * 8;
            bh = d_Ath; bl = d_Atl;
        } else {
            int u = t - ACH;
            int row = u >> 7, c8 = u & 127;
            src = imgs + (size_t)row * D_ + c8 * 8;
            dsto = (size_t)row * D_ + c8 * 8;
            bh = d_Bth; bl = d_Btl;
        }
        float4 v0 = *reinterpret_cast<const float4*>(src);
        float4 v1 = *reinterpret_cast<const float4*>(src + 4);
        float v[8] = {v0.x, v0.y, v0.z, v0.w, v1.x, v1.y, v1.z, v1.w};
        union { __nv_bfloat16 h[8]; uint4 u; } Hi, Lo;
        #pragma unroll
        for (int k = 0; k < 8; k++) {
            __nv_bfloat16 hb = __float2bfloat16(v[k]);
            float r = v[k] - __bfloat162float(hb);
            Hi.h[k] = hb;
            Lo.h[k] = __float2bfloat16(r);
        }
        *reinterpret_cast<uint4*>(bh + dsto) = Hi.u;
        *reinterpret_cast<uint4*>(bl + dsto) = Lo.u;
        return;
    }
    // capn + masked outputs + act total
    {
        int c = b - CONVB;
        int w = tid >> 3, l = tid & 7;
        const float* p = caps + ((size_t)(c * W_ + w)) * D_;
        float s = 0.f;
        for (int d = l; d < D_; d += 8) { float v = p[d]; s += v * v; }
        s += __shfl_down_sync(0xffffffffu, s, 4);
        s += __shfl_down_sync(0xffffffffu, s, 2);
        s += __shfl_down_sync(0xffffffffu, s, 1);
        if (l == 0) d_capn[c * W_ + w] = s;

        if (c == 0 && tid == 0) {
            int run = 0;
            for (int j = 0; j < C_; j++) run += cap_lens[j];
            d_act_total = run;
        }
        int nw = cap_lens[c];
        for (int idx = tid; idx < I_ * W_; idx += 256) {
            int i = idx >> 5, ww = idx & 31;
            if (ww >= nw)
                out[((size_t)i * C_ + c) * W_ + ww] = MASK_VAL_;
        }
    }
}

// ============================================================
// HMMA bf16x3 GEMM (BM=64) + gram partials in tail blocks
// 1D grid: [0,576) gemm tiles, [576,1088) gram
// ============================================================
__global__ void __launch_bounds__(256, 2) gemm_mma_kernel(const float* __restrict__ imgs) {
    extern __shared__ __align__(128) char smc[];
    int tid = threadIdx.x;
    int b = blockIdx.x;

    if (b >= GEMMB) {
        // ---- gram block (reuses dynamic smem) ----
        int gb = b - GEMMB;
        int i = gb >> 3, ch = gb & 7;
        float* sm = reinterpret_cast<float*>(smc);   // [36][132]
        const float* base = imgs + (size_t)i * R_ * D_ + ch * 128;
        for (int idx = tid; idx < R_ * 32; idx += 256) {
            int r = idx >> 5, d4 = idx & 31;
            float4 v = *reinterpret_cast<const float4*>(base + r * D_ + d4 * 4);
            *reinterpret_cast<float4*>(&sm[r * 132 + d4 * 4]) = v;
        }
        __syncthreads();
        if (tid < 144) {
            int tr = tid / 12, tc = tid % 12;
            float acc[3][3] = {};
            #pragma unroll 2
            for (int d = 0; d < 128; d += 4) {
                float4 A0 = *reinterpret_cast<const float4*>(&sm[(tr*3+0)*132 + d]);
                float4 A1 = *reinterpret_cast<const float4*>(&sm[(tr*3+1)*132 + d]);
                float4 A2 = *reinterpret_cast<const float4*>(&sm[(tr*3+2)*132 + d]);
                float4 B0 = *reinterpret_cast<const float4*>(&sm[(tc*3+0)*132 + d]);
                float4 B1 = *reinterpret_cast<const float4*>(&sm[(tc*3+1)*132 + d]);
                float4 B2 = *reinterpret_cast<const float4*>(&sm[(tc*3+2)*132 + d]);
                acc[0][0] = fmaf(A0.x,B0.x,fmaf(A0.y,B0.y,fmaf(A0.z,B0.z,fmaf(A0.w,B0.w,acc[0][0]))));
                acc[0][1] = fmaf(A0.x,B1.x,fmaf(A0.y,B1.y,fmaf(A0.z,B1.z,fmaf(A0.w,B1.w,acc[0][1]))));
                acc[0][2] = fmaf(A0.x,B2.x,fmaf(A0.y,B2.y,fmaf(A0.z,B2.z,fmaf(A0.w,B2.w,acc[0][2]))));
                acc[1][0] = fmaf(A1.x,B0.x,fmaf(A1.y,B0.y,fmaf(A1.z,B0.z,fmaf(A1.w,B0.w,acc[1][0]))));
                acc[1][1] = fmaf(A1.x,B1.x,fmaf(A1.y,B1.y,fmaf(A1.z,B1.z,fmaf(A1.w,B1.w,acc[1][1]))));
                acc[1][2] = fmaf(A1.x,B2.x,fmaf(A1.y,B2.y,fmaf(A1.z,B2.z,fmaf(A1.w,B2.w,acc[1][2]))));
                acc[2][0] = fmaf(A2.x,B0.x,fmaf(A2.y,B0.y,fmaf(A2.z,B0.z,fmaf(A2.w,B0.w,acc[2][0]))));
                acc[2][1] = fmaf(A2.x,B1.x,fmaf(A2.y,B1.y,fmaf(A2.z,B1.z,fmaf(A2.w,B1.w,acc[2][1]))));
                acc[2][2] = fmaf(A2.x,B2.x,fmaf(A2.y,B2.y,fmaf(A2.z,B2.z,fmaf(A2.w,B2.w,acc[2][2]))));
            }
            float* dst = d_Gp[ch] + i * (R_*R_);
            #pragma unroll
            for (int a = 0; a < 3; a++)
                #pragma unroll
                for (int bb = 0; bb < 3; bb++)
                    dst[(tr*3+a) * R_ + (tc*3+bb)] = acc[a][bb];
        }
        return;
    }

    uint32_t sb = smem_u32(smc);
    int wid = tid >> 5, lane = tid & 31;

    int act = d_act_total;
    int mblk = b / NB2, nblk = b % NB2;
    if (mblk * BM >= act) return;

    int wr = wid & 1, wc = wid >> 1;

    const __nv_bfloat16* srcA[2] = {
        d_Ath + (size_t)mblk * BM * D_,
        d_Atl + (size_t)mblk * BM * D_
    };
    const __nv_bfloat16* srcB[2] = {
        d_Bth + (size_t)nblk * BN * D_,
        d_Btl + (size_t)nblk * BN * D_
    };

    int q = lane >> 3, lr = lane & 7;
    int rowoff = ((q & 1) << 3) + lr;
    int csel = q >> 1;
    uint32_t aoff = (uint32_t)((wr * 32 + rowoff) * ROWB + csel * 16);
    uint32_t boff = (uint32_t)((wc * 32 + rowoff) * ROWB + csel * 16);

    float acc[2][4][4] = {};

    #define LOAD_STAGE(s, k0) do {                                              \
        _Pragma("unroll")                                                        \
        for (int it = 0; it < 6; it++) {                                         \
            int ci = tid + it * 256;                                             \
            const char* g; uint32_t dd;                                          \
            if (ci < 512) {                                                      \
                int tt = ci >> 8, r2 = ci & 255;                                  \
                int row = r2 >> 2, cc = r2 & 3;                                   \
                g = (const char*)(srcA[tt] + (size_t)row * D_ + (k0)) + cc * 16;  \
                dd = sb + (uint32_t)((s) * STGB + tt * TA + row * ROWB + cc * 16);\
            } else {                                                              \
                int u = ci - 512;                                                 \
                int tt = u >> 9, r2 = u & 511;                                    \
                int row = r2 >> 2, cc = r2 & 3;                                   \
                g = (const char*)(srcB[tt] + (size_t)row * D_ + (k0)) + cc * 16;  \
                dd = sb + (uint32_t)((s) * STGB + 2 * TA + tt * TB + row * ROWB + cc * 16); \
            }                                                                     \
            cpasync16(dd, g);                                                     \
        }                                                                         \
        CP_COMMIT();                                                              \
    } while (0)

    LOAD_STAGE(0, 0);

    for (int ks = 0; ks < NSTAGE; ks++) {
        int s = ks & 1;
        if (ks + 1 < NSTAGE) { LOAD_STAGE(s ^ 1, (ks + 1) * BK); CP_WAIT(1); }
        else                 { CP_WAIT(0); }
        __syncthreads();

        uint32_t bAh = sb + (uint32_t)(s * STGB);
        uint32_t bAl = bAh + TA;
        uint32_t bBh = bAh + 2 * TA;
        uint32_t bBl = bBh + TB;

        #pragma unroll
        for (int k16 = 0; k16 < 2; k16++) {
            uint32_t kb = (uint32_t)(k16 * 32);
            uint32_t ah[2][4], al[2][4];
            uint32_t bhf[4][2], blf[4][2];
            #pragma unroll
            for (int mt = 0; mt < 2; mt++) {
                ldsm4(ah[mt], bAh + (uint32_t)(mt * 16 * ROWB) + kb + aoff);
                ldsm4(al[mt], bAl + (uint32_t)(mt * 16 * ROWB) + kb + aoff);
            }
            #pragma unroll
            for (int np = 0; np < 2; np++) {
                uint32_t t4[4];
                ldsm4(t4, bBh + (uint32_t)(np * 16 * ROWB) + kb + boff);
                bhf[np*2+0][0] = t4[0]; bhf[np*2+0][1] = t4[2];
                bhf[np*2+1][0] = t4[1]; bhf[np*2+1][1] = t4[3];
                ldsm4(t4, bBl + (uint32_t)(np * 16 * ROWB) + kb + boff);
                blf[np*2+0][0] = t4[0]; blf[np*2+0][1] = t4[2];
                blf[np*2+1][0] = t4[1]; blf[np*2+1][1] = t4[3];
            }
            #pragma unroll
            for (int mt = 0; mt < 2; mt++)
                #pragma unroll
                for (int nt = 0; nt < 4; nt++) {
                    mma16816(acc[mt][nt], ah[mt], &bhf[nt][0], &bhf[nt][1]);
                    mma16816(acc[mt][nt], ah[mt], &blf[nt][0], &blf[nt][1]);
                    mma16816(acc[mt][nt], al[mt], &bhf[nt][0], &bhf[nt][1]);
                }
        }
        __syncthreads();
    }

    int g = lane >> 2, tq = lane & 3;
    #pragma unroll
    for (int mt = 0; mt < 2; mt++) {
        int m0 = mblk * BM + wr * 32 + mt * 16 + g;
        #pragma unroll
        for (int nt = 0; nt < 4; nt++) {
            int n = nblk * BN + wc * 32 + nt * 8 + tq * 2;
            if (m0 < act)
                *reinterpret_cast<float2*>(d_S + (size_t)m0 * N_ + n) =
                    make_float2(acc[mt][nt][0], acc[mt][nt][1]);
            if (m0 + 8 < act)
                *reinterpret_cast<float2*>(d_S + (size_t)(m0 + 8) * N_ + n) =
                    make_float2(acc[mt][nt][2], acc[mt][nt][3]);
        }
    }
}

// ============================================================
// post2: fused G-reduce + norms + softmax + symmetric quad form.
// ============================================================
__global__ void __launch_bounds__(256, 3) post2_kernel(const int* __restrict__ cap_lens,
                                                       float* __restrict__ out) {
    extern __shared__ float dyn[];
    float* Gs  = dyn + P2_GS;            // [36][36]
    float* Ss  = dyn + P2_SS;            // [8][32][37] flat
    float* rcn = dyn + P2_RCN;           // [64][38]
    __shared__ int cl[C_], offs[C_ + 1];

    int i = blockIdx.x;
    int tid = threadIdx.x, wid = tid >> 5, lane = tid & 31;

    compute_offs(cap_lens, cl, offs, tid);
    int act = offs[C_];
    int base0 = blockIdx.y * 256;
    if (base0 >= act) return;

    // reduce gram partials while loading G
    for (int idx = tid; idx < R_ * R_; idx += 256) {
        float s = 0.f;
        #pragma unroll
        for (int p = 0; p < GCH; p++) s += d_Gp[p][i * (R_*R_) + idx];
        Gs[idx] = s;
    }

    int blk_rows = act - base0;
    if (blk_rows > 256) blk_rows = 256;

    // stage S rows (warp per 32 rows)
    {
        int m0w = base0 + wid * 32;
        int nrows = act - m0w;
        if (nrows > 32) nrows = 32;
        if (nrows < 0) nrows = 0;
        for (int idx = lane; idx < nrows * R_; idx += 32) {
            int row = idx / R_, r = idx - row * R_;
            Ss[(wid * 32 + row) * 37 + r] = d_S[(size_t)(m0w + row) * N_ + i * R_ + r];
        }
    }
    __syncthreads();

    // fused norms: rcn for all c's overlapping this block's rows
    int c_lo = find_c(offs, base0);
    int c_hi = find_c(offs, base0 + blk_rows - 1);
    int ncs = c_hi - c_lo + 1;           // <= 64
    for (int item = tid; item < ncs * R_; item += 256) {
        int ci = item / R_, r = item - ci * R_;
        int c = c_lo + ci;
        int o = offs[c], nw2 = offs[c + 1] - o;
        float s = 0.f;
        for (int w = 0; w < nw2; w++) {
            int row = o + w;
            int lr2 = row - base0;
            float v = (lr2 >= 0 && lr2 < 256) ? Ss[lr2 * 37 + r]
                                              : d_S[(size_t)row * N_ + i * R_ + r];
            v = (v >= 0.f) ? v : 0.1f * v;
            s = fmaf(v, v, s);
        }
        rcn[ci * 38 + r] = SMOOTH_ / (sqrtf(s) + EPS_);
    }
    __syncthreads();

    int myrow = base0 + wid * 32 + lane;
    if (myrow < act && (wid * 32 + lane) < blk_rows) {
        int c = find_c(offs, myrow);
        int w = myrow - offs[c];
        const float* rc = rcn + (c - c_lo) * 38;
        const float* sr = Ss + (wid * 32 + lane) * 37;

        float a[R_];
        float sum0 = 0.f, sum1 = 0.f, sum2 = 0.f, sum3 = 0.f;
        float sd0 = 0.f, sd1 = 0.f, sd2 = 0.f, sd3 = 0.f;
        #pragma unroll
        for (int r = 0; r < R_; r += 4) {
            float v0 = sr[r+0], v1 = sr[r+1];
            float v2 = sr[r+2], v3 = sr[r+3];
            float l0 = (v0 >= 0.f) ? v0 : 0.1f * v0;
            float l1 = (v1 >= 0.f) ? v1 : 0.1f * v1;
            float l2 = (v2 >= 0.f) ? v2 : 0.1f * v2;
            float l3 = (v3 >= 0.f) ? v3 : 0.1f * v3;
            float e0 = __expf(l0 * rc[r+0]);
            float e1 = __expf(l1 * rc[r+1]);
            float e2 = __expf(l2 * rc[r+2]);
            float e3 = __expf(l3 * rc[r+3]);
            a[r+0] = e0; a[r+1] = e1; a[r+2] = e2; a[r+3] = e3;
            sum0 += e0; sum1 += e1; sum2 += e2; sum3 += e3;
            sd0 = fmaf(e0, v0, sd0); sd1 = fmaf(e1, v1, sd1);
            sd2 = fmaf(e2, v2, sd2); sd3 = fmaf(e3, v3, sd3);
        }
        float sum = (sum0 + sum1) + (sum2 + sum3);
        float sd  = (sd0 + sd1) + (sd2 + sd3);
        float inv = 1.f / sum;

        float qd = 0.f, qo0 = 0.f, qo1 = 0.f;
        #pragma unroll
        for (int rg = 0; rg < 9; rg++) {
            #pragma unroll
            for (int aa = 0; aa < 4; aa++) {
                float4 g4 = *reinterpret_cast<const float4*>(&Gs[(4*rg+aa) * R_ + 4*rg]);
                float t = g4.x * a[4*rg+0];
                t = fmaf(g4.y, a[4*rg+1], t);
                t = fmaf(g4.z, a[4*rg+2], t);
                t = fmaf(g4.w, a[4*rg+3], t);
                qd = fmaf(a[4*rg+aa], t, qd);
            }
            #pragma unroll
            for (int cg = rg + 1; cg < 9; cg++) {
                #pragma unroll
                for (int aa = 0; aa < 4; aa++) {
                    float4 g4 = *reinterpret_cast<const float4*>(&Gs[(4*rg+aa) * R_ + 4*cg]);
                    float t = g4.x * a[4*cg+0];
                    t = fmaf(g4.y, a[4*cg+1], t);
                    t = fmaf(g4.z, a[4*cg+2], t);
                    t = fmaf(g4.w, a[4*cg+3], t);
                    if ((cg ^ rg) & 1) qo0 = fmaf(a[4*rg+aa], t, qo0);
                    else               qo1 = fmaf(a[4*rg+aa], t, qo1);
                }
            }
        }
        float qe = qd + 2.f * (qo0 + qo1);

        float n = sqrtf(qe) * inv;
        float dot = sd * inv;
        float denom = n + EPS_;
        float w12 = dot / denom;
        float w2v = n / denom;
        float w1v = sqrtf(d_capn[c * W_ + w]);
        float sim = w12 / fmaxf(w1v * w2v, EPS_);
        out[((size_t)i * C_ + c) * W_ + w] = sim;
    }
}

// ============================================================
extern "C" void kernel_launch(void* const* d_in, const int* in_sizes, int n_in,
                              void* d_out, int out_size) {
    const float* imgs     = (const float*)d_in[0];
    const float* caps     = (const float*)d_in[1];
    const int*   cap_lens = (const int*)d_in[3];
    float* out = (float*)d_out;

    cudaFuncSetAttribute(gemm_mma_kernel, cudaFuncAttributeMaxDynamicSharedMemorySize, GEMM_SMEM);
    cudaFuncSetAttribute(post2_kernel, cudaFuncAttributeMaxDynamicSharedMemorySize, POST2_SMEM);

    mega_kernel<<<MEGAB, 256>>>(caps, imgs, cap_lens, out);
    gemm_mma_kernel<<<GEMMB + GRAMB, 256, GEMM_SMEM>>>(imgs);
    dim3 pgrid(I_, 8);
    post2_kernel<<<pgrid, 256, POST2_SMEM>>>(cap_lens, out);
}

// round 15
// speedup vs baseline: 1.2157x; 1.0887x over previous
#include <cuda_runtime.h>
#include <cuda_fp16.h>
#include <cstdint>
#include <math.h>

#define I_ 64
#define R_ 36
#define D_ 1024
#define C_ 64
#define W_ 32
#define N_ (I_*R_)       // 2304
#define MROWS (C_*W_)    // 2048
#define SMOOTH_ 9.0f
#define EPS_ 1e-8f
#define MASK_VAL_ (-1.0f)

// GEMM tiling (fp16 2-product: tiles Ah, Al, Bh)
#define BM 64
#define BN 128
#define BK 32
#define NSTAGE (D_/BK)           // 32
#define ROWB 80                  // 64B data + pad (ldsm conflict-free)
#define TA (BM*ROWB)             // 5120
#define TB (BN*ROWB)             // 10240
#define STGB (2*TA + TB)         // 20480
#define GEMM_SMEM (2*STGB)       // 40960
#define MB2 (MROWS/BM)           // 32
#define NB2 (N_/BN)              // 18
#define GEMMB (NB2*MB2)          // 576

// Gram k-split
#define GCH 8
#define GSZ (I_*R_*R_)           // 82944
#define GRAMB (I_ * GCH)         // 512

// mega-kernel partition (convert + capn)
#define ACH (MROWS * (D_/8))     // 262144
#define BCH (N_ * (D_/8))        // 294912
#define CONVB ((ACH + BCH) / 256) // 2176
#define CAPNB C_                  // 64
#define MEGAB (CONVB + CAPNB)

// post2 dynamic smem layout (floats)
#define P2_GS    0                        // [36][36]
#define P2_SS    (P2_GS + R_*R_)          // [8][32][37]
#define P2_RCN   (P2_SS + 8*32*37)        // [64][38]
#define P2_TOTAL (P2_RCN + 64*38)
#define POST2_SMEM (P2_TOTAL * 4)         // ~53KB

// ---- static scratch ----
__device__ float d_S[MROWS * N_];
__device__ float d_Gp[GCH][GSZ];
__device__ float d_capn[C_ * W_];
__device__ int   d_act_total;

__device__ __half d_Ah[MROWS * D_];
__device__ __half d_Al[MROWS * D_];
__device__ __half d_Bh[N_ * D_];

// ================= PTX helpers =================
__device__ __forceinline__ uint32_t smem_u32(const void* p) {
    uint32_t a;
    asm("{ .reg .u64 t; cvta.to.shared.u64 t, %1; cvt.u32.u64 %0, t; }" : "=r"(a) : "l"(p));
    return a;
}
__device__ __forceinline__ void cpasync16(uint32_t dst, const void* src) {
    asm volatile("cp.async.cg.shared.global [%0], [%1], 16;" :: "r"(dst), "l"(src) : "memory");
}
#define CP_COMMIT() asm volatile("cp.async.commit_group;" ::: "memory")
#define CP_WAIT(n)  asm volatile("cp.async.wait_group %0;" :: "n"(n) : "memory")

__device__ __forceinline__ void ldsm4(uint32_t r[4], uint32_t addr) {
    asm volatile("ldmatrix.sync.aligned.m8n8.x4.shared.b16 {%0,%1,%2,%3}, [%4];"
                 : "=r"(r[0]), "=r"(r[1]), "=r"(r[2]), "=r"(r[3]) : "r"(addr));
}
__device__ __forceinline__ void mma16816(float* d, const uint32_t* a, const uint32_t* b0, const uint32_t* b1) {
    asm volatile("mma.sync.aligned.m16n8k16.row.col.f32.f16.f16.f32 "
                 "{%0,%1,%2,%3},{%4,%5,%6,%7},{%8,%9},{%0,%1,%2,%3};"
                 : "+f"(d[0]), "+f"(d[1]), "+f"(d[2]), "+f"(d[3])
                 : "r"(a[0]), "r"(a[1]), "r"(a[2]), "r"(a[3]), "r"(*b0), "r"(*b1));
}

// block-local exclusive scan of cap_lens into offs[0..64] (parallel)
__device__ __forceinline__ void compute_offs(const int* __restrict__ cap_lens,
                                             int* cl, int* offs, int tid) {
    if (tid < C_) cl[tid] = cap_lens[tid];
    __syncthreads();
    if (tid <= C_) {
        int run = 0;
        for (int j = 0; j < tid; j++) run += cl[j];
        offs[tid] = run;
    }
    __syncthreads();
}
__device__ __forceinline__ int find_c(const int* offs, int row) {
    int lo = 0, hi = C_;
    #pragma unroll
    for (int it = 0; it < 6; it++) {
        int mid = (lo + hi) >> 1;
        if (offs[mid] <= row) lo = mid; else hi = mid;
    }
    return lo;
}

// ============================================================
// mega kernel: convert + capn(+mask+act)
// ============================================================
__global__ void __launch_bounds__(256) mega_kernel(const float* __restrict__ caps,
                                                   const float* __restrict__ imgs,
                                                   const int* __restrict__ cap_lens,
                                                   float* __restrict__ out) {
    __shared__ int cl[C_], offs[C_ + 1];
    int b = blockIdx.x, tid = threadIdx.x;

    if (b < CONVB) {
        int t = b * 256 + tid;
        if (t < ACH) {
            // A: gathered, split hi/lo fp16
            compute_offs(cap_lens, cl, offs, tid);
            int row = t >> 7, c8 = t & 127;
            int act = offs[C_];
            int srcrow = 0;
            if (row < act) {
                int c = find_c(offs, row);
                srcrow = c * W_ + (row - offs[c]);
            }
            const float* src = caps + (size_t)srcrow * D_ + c8 * 8;
            size_t dsto = (size_t)row * D_ + c8 * 8;
            float4 v0 = *reinterpret_cast<const float4*>(src);
            float4 v1 = *reinterpret_cast<const float4*>(src + 4);
            float v[8] = {v0.x, v0.y, v0.z, v0.w, v1.x, v1.y, v1.z, v1.w};
            union { __half h[8]; uint4 u; } Hi, Lo;
            #pragma unroll
            for (int k = 0; k < 8; k++) {
                __half hb = __float2half_rn(v[k]);
                float r = v[k] - __half2float(hb);
                Hi.h[k] = hb;
                Lo.h[k] = __float2half_rn(r);
            }
            *reinterpret_cast<uint4*>(d_Ah + dsto) = Hi.u;
            *reinterpret_cast<uint4*>(d_Al + dsto) = Lo.u;
        } else {
            // B: single fp16
            int u = t - ACH;
            int row = u >> 7, c8 = u & 127;
            const float* src = imgs + (size_t)row * D_ + c8 * 8;
            size_t dsto = (size_t)row * D_ + c8 * 8;
            float4 v0 = *reinterpret_cast<const float4*>(src);
            float4 v1 = *reinterpret_cast<const float4*>(src + 4);
            float v[8] = {v0.x, v0.y, v0.z, v0.w, v1.x, v1.y, v1.z, v1.w};
            union { __half h[8]; uint4 u; } Hi;
            #pragma unroll
            for (int k = 0; k < 8; k++) Hi.h[k] = __float2half_rn(v[k]);
            *reinterpret_cast<uint4*>(d_Bh + dsto) = Hi.u;
        }
        return;
    }
    // capn + masked outputs + act total
    {
        int c = b - CONVB;
        int w = tid >> 3, l = tid & 7;
        const float* p = caps + ((size_t)(c * W_ + w)) * D_;
        float s = 0.f;
        for (int d = l; d < D_; d += 8) { float v = p[d]; s += v * v; }
        s += __shfl_down_sync(0xffffffffu, s, 4);
        s += __shfl_down_sync(0xffffffffu, s, 2);
        s += __shfl_down_sync(0xffffffffu, s, 1);
        if (l == 0) d_capn[c * W_ + w] = s;

        if (c == 0 && tid == 0) {
            int run = 0;
            for (int j = 0; j < C_; j++) run += cap_lens[j];
            d_act_total = run;
        }
        int nw = cap_lens[c];
        for (int idx = tid; idx < I_ * W_; idx += 256) {
            int i = idx >> 5, ww = idx & 31;
            if (ww >= nw)
                out[((size_t)i * C_ + c) * W_ + ww] = MASK_VAL_;
        }
    }
}

// ============================================================
// HMMA fp16 2-product GEMM (BM=64, 3 CTAs/SM) + gram tail blocks
// 1D grid: [0,576) gemm tiles, [576,1088) gram
// ============================================================
__global__ void __launch_bounds__(256, 3) gemm_mma_kernel(const float* __restrict__ imgs) {
    extern __shared__ __align__(128) char smc[];
    int tid = threadIdx.x;
    int b = blockIdx.x;

    if (b >= GEMMB) {
        // ---- gram block (reuses dynamic smem: 36*132*4 = 19008 < 40960) ----
        int gb = b - GEMMB;
        int i = gb >> 3, ch = gb & 7;
        float* sm = reinterpret_cast<float*>(smc);   // [36][132]
        const float* base = imgs + (size_t)i * R_ * D_ + ch * 128;
        for (int idx = tid; idx < R_ * 32; idx += 256) {
            int r = idx >> 5, d4 = idx & 31;
            float4 v = *reinterpret_cast<const float4*>(base + r * D_ + d4 * 4);
            *reinterpret_cast<float4*>(&sm[r * 132 + d4 * 4]) = v;
        }
        __syncthreads();
        if (tid < 144) {
            int tr = tid / 12, tc = tid % 12;
            float acc[3][3] = {};
            #pragma unroll 2
            for (int d = 0; d < 128; d += 4) {
                float4 A0 = *reinterpret_cast<const float4*>(&sm[(tr*3+0)*132 + d]);
                float4 A1 = *reinterpret_cast<const float4*>(&sm[(tr*3+1)*132 + d]);
                float4 A2 = *reinterpret_cast<const float4*>(&sm[(tr*3+2)*132 + d]);
                float4 B0 = *reinterpret_cast<const float4*>(&sm[(tc*3+0)*132 + d]);
                float4 B1 = *reinterpret_cast<const float4*>(&sm[(tc*3+1)*132 + d]);
                float4 B2 = *reinterpret_cast<const float4*>(&sm[(tc*3+2)*132 + d]);
                acc[0][0] = fmaf(A0.x,B0.x,fmaf(A0.y,B0.y,fmaf(A0.z,B0.z,fmaf(A0.w,B0.w,acc[0][0]))));
                acc[0][1] = fmaf(A0.x,B1.x,fmaf(A0.y,B1.y,fmaf(A0.z,B1.z,fmaf(A0.w,B1.w,acc[0][1]))));
                acc[0][2] = fmaf(A0.x,B2.x,fmaf(A0.y,B2.y,fmaf(A0.z,B2.z,fmaf(A0.w,B2.w,acc[0][2]))));
                acc[1][0] = fmaf(A1.x,B0.x,fmaf(A1.y,B0.y,fmaf(A1.z,B0.z,fmaf(A1.w,B0.w,acc[1][0]))));
                acc[1][1] = fmaf(A1.x,B1.x,fmaf(A1.y,B1.y,fmaf(A1.z,B1.z,fmaf(A1.w,B1.w,acc[1][1]))));
                acc[1][2] = fmaf(A1.x,B2.x,fmaf(A1.y,B2.y,fmaf(A1.z,B2.z,fmaf(A1.w,B2.w,acc[1][2]))));
                acc[2][0] = fmaf(A2.x,B0.x,fmaf(A2.y,B0.y,fmaf(A2.z,B0.z,fmaf(A2.w,B0.w,acc[2][0]))));
                acc[2][1] = fmaf(A2.x,B1.x,fmaf(A2.y,B1.y,fmaf(A2.z,B1.z,fmaf(A2.w,B1.w,acc[2][1]))));
                acc[2][2] = fmaf(A2.x,B2.x,fmaf(A2.y,B2.y,fmaf(A2.z,B2.z,fmaf(A2.w,B2.w,acc[2][2]))));
            }
            float* dst = d_Gp[ch] + i * (R_*R_);
            #pragma unroll
            for (int a = 0; a < 3; a++)
                #pragma unroll
                for (int bb = 0; bb < 3; bb++)
                    dst[(tr*3+a) * R_ + (tc*3+bb)] = acc[a][bb];
        }
        return;
    }

    uint32_t sb = smem_u32(smc);
    int wid = tid >> 5, lane = tid & 31;

    int act = d_act_total;
    int mblk = b / NB2, nblk = b % NB2;
    if (mblk * BM >= act) return;

    int wr = wid & 1, wc = wid >> 1;

    const __half* srcA[2] = {
        d_Ah + (size_t)mblk * BM * D_,
        d_Al + (size_t)mblk * BM * D_
    };
    const __half* srcB = d_Bh + (size_t)nblk * BN * D_;

    int q = lane >> 3, lr = lane & 7;
    int rowoff = ((q & 1) << 3) + lr;
    int csel = q >> 1;
    uint32_t aoff = (uint32_t)((wr * 32 + rowoff) * ROWB + csel * 16);
    uint32_t boff = (uint32_t)((wc * 32 + rowoff) * ROWB + csel * 16);

    float acc[2][4][4] = {};

    // per stage: Ah 256 + Al 256 + Bh 512 = 1024 chunks(16B); 4/thread
    #define LOAD_STAGE(s, k0) do {                                              \
        _Pragma("unroll")                                                        \
        for (int it = 0; it < 4; it++) {                                         \
            int ci = tid + it * 256;                                             \
            const char* g; uint32_t dd;                                          \
            if (ci < 512) {                                                      \
                int tt = ci >> 8, r2 = ci & 255;                                  \
                int row = r2 >> 2, cc = r2 & 3;                                   \
                g = (const char*)(srcA[tt] + (size_t)row * D_ + (k0)) + cc * 16;  \
                dd = sb + (uint32_t)((s) * STGB + tt * TA + row * ROWB + cc * 16);\
            } else {                                                              \
                int u = ci - 512;                                                 \
                int row = u >> 2, cc = u & 3;                                     \
                g = (const char*)(srcB + (size_t)row * D_ + (k0)) + cc * 16;      \
                dd = sb + (uint32_t)((s) * STGB + 2 * TA + row * ROWB + cc * 16); \
            }                                                                     \
            cpasync16(dd, g);                                                     \
        }                                                                         \
        CP_COMMIT();                                                              \
    } while (0)

    LOAD_STAGE(0, 0);

    for (int ks = 0; ks < NSTAGE; ks++) {
        int s = ks & 1;
        if (ks + 1 < NSTAGE) { LOAD_STAGE(s ^ 1, (ks + 1) * BK); CP_WAIT(1); }
        else                 { CP_WAIT(0); }
        __syncthreads();

        uint32_t bAh = sb + (uint32_t)(s * STGB);
        uint32_t bAl = bAh + TA;
        uint32_t bBh = bAh + 2 * TA;

        #pragma unroll
        for (int k16 = 0; k16 < 2; k16++) {
            uint32_t kb = (uint32_t)(k16 * 32);
            uint32_t ah[2][4], al[2][4];
            uint32_t bhf[4][2];
            #pragma unroll
            for (int mt = 0; mt < 2; mt++) {
                ldsm4(ah[mt], bAh + (uint32_t)(mt * 16 * ROWB) + kb + aoff);
                ldsm4(al[mt], bAl + (uint32_t)(mt * 16 * ROWB) + kb + aoff);
            }
            #pragma unroll
            for (int np = 0; np < 2; np++) {
                uint32_t t4[4];
                ldsm4(t4, bBh + (uint32_t)(np * 16 * ROWB) + kb + boff);
                bhf[np*2+0][0] = t4[0]; bhf[np*2+0][1] = t4[2];
                bhf[np*2+1][0] = t4[1]; bhf[np*2+1][1] = t4[3];
            }
            #pragma unroll
            for (int mt = 0; mt < 2; mt++)
                #pragma unroll
                for (int nt = 0; nt < 4; nt++) {
                    mma16816(acc[mt][nt], ah[mt], &bhf[nt][0], &bhf[nt][1]);
                    mma16816(acc[mt][nt], al[mt], &bhf[nt][0], &bhf[nt][1]);
                }
        }
        __syncthreads();
    }

    int g = lane >> 2, tq = lane & 3;
    #pragma unroll
    for (int mt = 0; mt < 2; mt++) {
        int m0 = mblk * BM + wr * 32 + mt * 16 + g;
        #pragma unroll
        for (int nt = 0; nt < 4; nt++) {
            int n = nblk * BN + wc * 32 + nt * 8 + tq * 2;
            if (m0 < act)
                *reinterpret_cast<float2*>(d_S + (size_t)m0 * N_ + n) =
                    make_float2(acc[mt][nt][0], acc[mt][nt][1]);
            if (m0 + 8 < act)
                *reinterpret_cast<float2*>(d_S + (size_t)(m0 + 8) * N_ + n) =
                    make_float2(acc[mt][nt][2], acc[mt][nt][3]);
        }
    }
}

// ============================================================
// post2: fused G-reduce + norms + softmax + symmetric quad form.
// ============================================================
__global__ void __launch_bounds__(256, 3) post2_kernel(const int* __restrict__ cap_lens,
                                                       float* __restrict__ out) {
    extern __shared__ float dyn[];
    float* Gs  = dyn + P2_GS;            // [36][36]
    float* Ss  = dyn + P2_SS;            // [8][32][37] flat
    float* rcn = dyn + P2_RCN;           // [64][38]
    __shared__ int cl[C_], offs[C_ + 1];

    int i = blockIdx.x;
    int tid = threadIdx.x, wid = tid >> 5, lane = tid & 31;

    compute_offs(cap_lens, cl, offs, tid);
    int act = offs[C_];
    int base0 = blockIdx.y * 256;
    if (base0 >= act) return;

    // reduce gram partials while loading G
    for (int idx = tid; idx < R_ * R_; idx += 256) {
        float s = 0.f;
        #pragma unroll
        for (int p = 0; p < GCH; p++) s += d_Gp[p][i * (R_*R_) + idx];
        Gs[idx] = s;
    }

    int blk_rows = act - base0;
    if (blk_rows > 256) blk_rows = 256;

    // stage S rows (warp per 32 rows)
    {
        int m0w = base0 + wid * 32;
        int nrows = act - m0w;
        if (nrows > 32) nrows = 32;
        if (nrows < 0) nrows = 0;
        for (int idx = lane; idx < nrows * R_; idx += 32) {
            int row = idx / R_, r = idx - row * R_;
            Ss[(wid * 32 + row) * 37 + r] = d_S[(size_t)(m0w + row) * N_ + i * R_ + r];
        }
    }
    __syncthreads();

    // fused norms: rcn for all c's overlapping this block's rows
    int c_lo = find_c(offs, base0);
    int c_hi = find_c(offs, base0 + blk_rows - 1);
    int ncs = c_hi - c_lo + 1;           // <= 64
    for (int item = tid; item < ncs * R_; item += 256) {
        int ci = item / R_, r = item - ci * R_;
        int c = c_lo + ci;
        int o = offs[c], nw2 = offs[c + 1] - o;
        float s = 0.f;
        for (int w = 0; w < nw2; w++) {
            int row = o + w;
            int lr2 = row - base0;
            float v = (lr2 >= 0 && lr2 < 256) ? Ss[lr2 * 37 + r]
                                              : d_S[(size_t)row * N_ + i * R_ + r];
            v = (v >= 0.f) ? v : 0.1f * v;
            s = fmaf(v, v, s);
        }
        rcn[ci * 38 + r] = SMOOTH_ / (sqrtf(s) + EPS_);
    }
    __syncthreads();

    int myrow = base0 + wid * 32 + lane;
    if (myrow < act && (wid * 32 + lane) < blk_rows) {
        int c = find_c(offs, myrow);
        int w = myrow - offs[c];
        const float* rc = rcn + (c - c_lo) * 38;
        const float* sr = Ss + (wid * 32 + lane) * 37;

        float a[R_];
        float sum0 = 0.f, sum1 = 0.f, sum2 = 0.f, sum3 = 0.f;
        float sd0 = 0.f, sd1 = 0.f, sd2 = 0.f, sd3 = 0.f;
        #pragma unroll
        for (int r = 0; r < R_; r += 4) {
            float v0 = sr[r+0], v1 = sr[r+1];
            float v2 = sr[r+2], v3 = sr[r+3];
            float l0 = (v0 >= 0.f) ? v0 : 0.1f * v0;
            float l1 = (v1 >= 0.f) ? v1 : 0.1f * v1;
            float l2 = (v2 >= 0.f) ? v2 : 0.1f * v2;
            float l3 = (v3 >= 0.f) ? v3 : 0.1f * v3;
            float e0 = __expf(l0 * rc[r+0]);
            float e1 = __expf(l1 * rc[r+1]);
            float e2 = __expf(l2 * rc[r+2]);
            float e3 = __expf(l3 * rc[r+3]);
            a[r+0] = e0; a[r+1] = e1; a[r+2] = e2; a[r+3] = e3;
            sum0 += e0; sum1 += e1; sum2 += e2; sum3 += e3;
            sd0 = fmaf(e0, v0, sd0); sd1 = fmaf(e1, v1, sd1);
            sd2 = fmaf(e2, v2, sd2); sd3 = fmaf(e3, v3, sd3);
        }
        float sum = (sum0 + sum1) + (sum2 + sum3);
        float sd  = (sd0 + sd1) + (sd2 + sd3);
        float inv = 1.f / sum;

        float qd = 0.f, qo0 = 0.f, qo1 = 0.f;
        #pragma unroll
        for (int rg = 0; rg < 9; rg++) {
            #pragma unroll
            for (int aa = 0; aa < 4; aa++) {
                float4 g4 = *reinterpret_cast<const float4*>(&Gs[(4*rg+aa) * R_ + 4*rg]);
                float t = g4.x * a[4*rg+0];
                t = fmaf(g4.y, a[4*rg+1], t);
                t = fmaf(g4.z, a[4*rg+2], t);
                t = fmaf(g4.w, a[4*rg+3], t);
                qd = fmaf(a[4*rg+aa], t, qd);
            }
            #pragma unroll
            for (int cg = rg + 1; cg < 9; cg++) {
                #pragma unroll
                for (int aa = 0; aa < 4; aa++) {
                    float4 g4 = *reinterpret_cast<const float4*>(&Gs[(4*rg+aa) * R_ + 4*cg]);
                    float t = g4.x * a[4*cg+0];
                    t = fmaf(g4.y, a[4*cg+1], t);
                    t = fmaf(g4.z, a[4*cg+2], t);
                    t = fmaf(g4.w, a[4*cg+3], t);
                    if ((cg ^ rg) & 1) qo0 = fmaf(a[4*rg+aa], t, qo0);
                    else               qo1 = fmaf(a[4*rg+aa], t, qo1);
                }
            }
        }
        float qe = qd + 2.f * (qo0 + qo1);

        float n = sqrtf(qe) * inv;
        float dot = sd * inv;
        float denom = n + EPS_;
        float w12 = dot / denom;
        float w2v = n / denom;
        float w1v = sqrtf(d_capn[c * W_ + w]);
        float sim = w12 / fmaxf(w1v * w2v, EPS_);
        out[((size_t)i * C_ + c) * W_ + w] = sim;
    }
}

// ============================================================
extern "C" void kernel_launch(void* const* d_in, const int* in_sizes, int n_in,
                              void* d_out, int out_size) {
    const float* imgs     = (const float*)d_in[0];
    const float* caps     = (const float*)d_in[1];
    const int*   cap_lens = (const int*)d_in[3];
    float* out = (float*)d_out;

    cudaFuncSetAttribute(gemm_mma_kernel, cudaFuncAttributeMaxDynamicSharedMemorySize, GEMM_SMEM);
    cudaFuncSetAttribute(post2_kernel, cudaFuncAttributeMaxDynamicSharedMemorySize, POST2_SMEM);

    mega_kernel<<<MEGAB, 256>>>(caps, imgs, cap_lens, out);
    gemm_mma_kernel<<<GEMMB + GRAMB, 256, GEMM_SMEM>>>(imgs);
    dim3 pgrid(I_, 8);
    post2_kernel<<<pgrid, 256, POST2_SMEM>>>(cap_lens, out);
}

// round 16
// speedup vs baseline: 1.5538x; 1.2781x over previous
#include <cuda_runtime.h>
#include <cuda_fp16.h>
#include <cstdint>
#include <math.h>

#define I_ 64
#define R_ 36
#define D_ 1024
#define C_ 64
#define W_ 32
#define N_ (I_*R_)       // 2304
#define MROWS (C_*W_)    // 2048
#define SMOOTH_ 9.0f
#define EPS_ 1e-8f
#define MASK_VAL_ (-1.0f)

// GEMM tiling (fp16 single-product: tiles Ah, Bh)
#define BM 64
#define BN 128
#define BK 32
#define NSTAGE (D_/BK)           // 32
#define ROWB 80                  // 64B data + pad (ldsm conflict-free)
#define TA (BM*ROWB)             // 5120
#define TB (BN*ROWB)             // 10240
#define STGB (TA + TB)           // 15360
#define GEMM_SMEM (2*STGB)       // 30720
#define MB2 (MROWS/BM)           // 32
#define NB2 (N_/BN)              // 18
#define GEMMB (NB2*MB2)          // 576

// Gram k-split
#define GCH 8
#define GSZ (I_*R_*R_)           // 82944
#define GRAMB (I_ * GCH)         // 512

// mega-kernel partition (convert + capn)
#define ACH (MROWS * (D_/8))     // 262144
#define BCH (N_ * (D_/8))        // 294912
#define CONVB ((ACH + BCH) / 256) // 2176
#define CAPNB C_                  // 64
#define MEGAB (CONVB + CAPNB)

// post2 dynamic smem layout (floats)
#define P2_GS    0                        // [36][36]
#define P2_SS    (P2_GS + R_*R_)          // [8][32][37]
#define P2_RCN   (P2_SS + 8*32*37)        // [64][38]
#define P2_TOTAL (P2_RCN + 64*38)
#define POST2_SMEM (P2_TOTAL * 4)         // ~53KB

// ---- static scratch ----
__device__ float d_S[MROWS * N_];
__device__ float d_Gp[GCH][GSZ];
__device__ float d_capn[C_ * W_];
__device__ int   d_act_total;

__device__ __half d_Ah[MROWS * D_];
__device__ __half d_Bh[N_ * D_];

// ================= PTX helpers =================
__device__ __forceinline__ uint32_t smem_u32(const void* p) {
    uint32_t a;
    asm("{ .reg .u64 t; cvta.to.shared.u64 t, %1; cvt.u32.u64 %0, t; }" : "=r"(a) : "l"(p));
    return a;
}
__device__ __forceinline__ void cpasync16(uint32_t dst, const void* src) {
    asm volatile("cp.async.cg.shared.global [%0], [%1], 16;" :: "r"(dst), "l"(src) : "memory");
}
#define CP_COMMIT() asm volatile("cp.async.commit_group;" ::: "memory")
#define CP_WAIT(n)  asm volatile("cp.async.wait_group %0;" :: "n"(n) : "memory")

__device__ __forceinline__ void ldsm4(uint32_t r[4], uint32_t addr) {
    asm volatile("ldmatrix.sync.aligned.m8n8.x4.shared.b16 {%0,%1,%2,%3}, [%4];"
                 : "=r"(r[0]), "=r"(r[1]), "=r"(r[2]), "=r"(r[3]) : "r"(addr));
}
__device__ __forceinline__ void mma16816(float* d, const uint32_t* a, const uint32_t* b0, const uint32_t* b1) {
    asm volatile("mma.sync.aligned.m16n8k16.row.col.f32.f16.f16.f32 "
                 "{%0,%1,%2,%3},{%4,%5,%6,%7},{%8,%9},{%0,%1,%2,%3};"
                 : "+f"(d[0]), "+f"(d[1]), "+f"(d[2]), "+f"(d[3])
                 : "r"(a[0]), "r"(a[1]), "r"(a[2]), "r"(a[3]), "r"(*b0), "r"(*b1));
}

// block-local exclusive scan of cap_lens into offs[0..64] (parallel)
__device__ __forceinline__ void compute_offs(const int* __restrict__ cap_lens,
                                             int* cl, int* offs, int tid) {
    if (tid < C_) cl[tid] = cap_lens[tid];
    __syncthreads();
    if (tid <= C_) {
        int run = 0;
        for (int j = 0; j < tid; j++) run += cl[j];
        offs[tid] = run;
    }
    __syncthreads();
}
__device__ __forceinline__ int find_c(const int* offs, int row) {
    int lo = 0, hi = C_;
    #pragma unroll
    for (int it = 0; it < 6; it++) {
        int mid = (lo + hi) >> 1;
        if (offs[mid] <= row) lo = mid; else hi = mid;
    }
    return lo;
}

// ============================================================
// mega kernel: convert + capn(+mask+act)
// ============================================================
__global__ void __launch_bounds__(256) mega_kernel(const float* __restrict__ caps,
                                                   const float* __restrict__ imgs,
                                                   const int* __restrict__ cap_lens,
                                                   float* __restrict__ out) {
    __shared__ int cl[C_], offs[C_ + 1];
    int b = blockIdx.x, tid = threadIdx.x;

    if (b < CONVB) {
        int t = b * 256 + tid;
        const float* src;
        __half* dst;
        size_t dsto;
        if (t < ACH) {
            // A: gathered fp16
            compute_offs(cap_lens, cl, offs, tid);
            int row = t >> 7, c8 = t & 127;
            int act = offs[C_];
            int srcrow = 0;
            if (row < act) {
                int c = find_c(offs, row);
                srcrow = c * W_ + (row - offs[c]);
            }
            src = caps + (size_t)srcrow * D_ + c8 * 8;
            dsto = (size_t)row * D_ + c8 * 8;
            dst = d_Ah;
        } else {
            int u = t - ACH;
            int row = u >> 7, c8 = u & 127;
            src = imgs + (size_t)row * D_ + c8 * 8;
            dsto = (size_t)row * D_ + c8 * 8;
            dst = d_Bh;
        }
        float4 v0 = *reinterpret_cast<const float4*>(src);
        float4 v1 = *reinterpret_cast<const float4*>(src + 4);
        float v[8] = {v0.x, v0.y, v0.z, v0.w, v1.x, v1.y, v1.z, v1.w};
        union { __half h[8]; uint4 u; } Hi;
        #pragma unroll
        for (int k = 0; k < 8; k++) Hi.h[k] = __float2half_rn(v[k]);
        *reinterpret_cast<uint4*>(dst + dsto) = Hi.u;
        return;
    }
    // capn + masked outputs + act total
    {
        int c = b - CONVB;
        int w = tid >> 3, l = tid & 7;
        const float* p = caps + ((size_t)(c * W_ + w)) * D_;
        float s = 0.f;
        for (int d = l; d < D_; d += 8) { float v = p[d]; s += v * v; }
        s += __shfl_down_sync(0xffffffffu, s, 4);
        s += __shfl_down_sync(0xffffffffu, s, 2);
        s += __shfl_down_sync(0xffffffffu, s, 1);
        if (l == 0) d_capn[c * W_ + w] = s;

        if (c == 0 && tid == 0) {
            int run = 0;
            for (int j = 0; j < C_; j++) run += cap_lens[j];
            d_act_total = run;
        }
        int nw = cap_lens[c];
        for (int idx = tid; idx < I_ * W_; idx += 256) {
            int i = idx >> 5, ww = idx & 31;
            if (ww >= nw)
                out[((size_t)i * C_ + c) * W_ + ww] = MASK_VAL_;
        }
    }
}

// ============================================================
// HMMA fp16 single-product GEMM (BM=64, 4 CTAs/SM) + gram tail
// 1D grid: [0,576) gemm tiles, [576,1088) gram
// ============================================================
__global__ void __launch_bounds__(256, 4) gemm_mma_kernel(const float* __restrict__ imgs) {
    extern __shared__ __align__(128) char smc[];
    int tid = threadIdx.x;
    int b = blockIdx.x;

    if (b >= GEMMB) {
        // ---- gram block (reuses dynamic smem: 36*132*4 = 19008 < 30720) ----
        int gb = b - GEMMB;
        int i = gb >> 3, ch = gb & 7;
        float* sm = reinterpret_cast<float*>(smc);   // [36][132]
        const float* base = imgs + (size_t)i * R_ * D_ + ch * 128;
        for (int idx = tid; idx < R_ * 32; idx += 256) {
            int r = idx >> 5, d4 = idx & 31;
            float4 v = *reinterpret_cast<const float4*>(base + r * D_ + d4 * 4);
            *reinterpret_cast<float4*>(&sm[r * 132 + d4 * 4]) = v;
        }
        __syncthreads();
        if (tid < 144) {
            int tr = tid / 12, tc = tid % 12;
            float acc[3][3] = {};
            #pragma unroll 2
            for (int d = 0; d < 128; d += 4) {
                float4 A0 = *reinterpret_cast<const float4*>(&sm[(tr*3+0)*132 + d]);
                float4 A1 = *reinterpret_cast<const float4*>(&sm[(tr*3+1)*132 + d]);
                float4 A2 = *reinterpret_cast<const float4*>(&sm[(tr*3+2)*132 + d]);
                float4 B0 = *reinterpret_cast<const float4*>(&sm[(tc*3+0)*132 + d]);
                float4 B1 = *reinterpret_cast<const float4*>(&sm[(tc*3+1)*132 + d]);
                float4 B2 = *reinterpret_cast<const float4*>(&sm[(tc*3+2)*132 + d]);
                acc[0][0] = fmaf(A0.x,B0.x,fmaf(A0.y,B0.y,fmaf(A0.z,B0.z,fmaf(A0.w,B0.w,acc[0][0]))));
                acc[0][1] = fmaf(A0.x,B1.x,fmaf(A0.y,B1.y,fmaf(A0.z,B1.z,fmaf(A0.w,B1.w,acc[0][1]))));
                acc[0][2] = fmaf(A0.x,B2.x,fmaf(A0.y,B2.y,fmaf(A0.z,B2.z,fmaf(A0.w,B2.w,acc[0][2]))));
                acc[1][0] = fmaf(A1.x,B0.x,fmaf(A1.y,B0.y,fmaf(A1.z,B0.z,fmaf(A1.w,B0.w,acc[1][0]))));
                acc[1][1] = fmaf(A1.x,B1.x,fmaf(A1.y,B1.y,fmaf(A1.z,B1.z,fmaf(A1.w,B1.w,acc[1][1]))));
                acc[1][2] = fmaf(A1.x,B2.x,fmaf(A1.y,B2.y,fmaf(A1.z,B2.z,fmaf(A1.w,B2.w,acc[1][2]))));
                acc[2][0] = fmaf(A2.x,B0.x,fmaf(A2.y,B0.y,fmaf(A2.z,B0.z,fmaf(A2.w,B0.w,acc[2][0]))));
                acc[2][1] = fmaf(A2.x,B1.x,fmaf(A2.y,B1.y,fmaf(A2.z,B1.z,fmaf(A2.w,B1.w,acc[2][1]))));
                acc[2][2] = fmaf(A2.x,B2.x,fmaf(A2.y,B2.y,fmaf(A2.z,B2.z,fmaf(A2.w,B2.w,acc[2][2]))));
            }
            float* dst = d_Gp[ch] + i * (R_*R_);
            #pragma unroll
            for (int a = 0; a < 3; a++)
                #pragma unroll
                for (int bb = 0; bb < 3; bb++)
                    dst[(tr*3+a) * R_ + (tc*3+bb)] = acc[a][bb];
        }
        return;
    }

    uint32_t sb = smem_u32(smc);
    int wid = tid >> 5, lane = tid & 31;

    int act = d_act_total;
    int mblk = b / NB2, nblk = b % NB2;
    if (mblk * BM >= act) return;

    int wr = wid & 1, wc = wid >> 1;

    const __half* srcA = d_Ah + (size_t)mblk * BM * D_;
    const __half* srcB = d_Bh + (size_t)nblk * BN * D_;

    int q = lane >> 3, lr = lane & 7;
    int rowoff = ((q & 1) << 3) + lr;
    int csel = q >> 1;
    uint32_t aoff = (uint32_t)((wr * 32 + rowoff) * ROWB + csel * 16);
    uint32_t boff = (uint32_t)((wc * 32 + rowoff) * ROWB + csel * 16);

    float acc[2][4][4] = {};

    // per stage: Ah 256 + Bh 512 = 768 chunks(16B); 3/thread
    #define LOAD_STAGE(s, k0) do {                                              \
        _Pragma("unroll")                                                        \
        for (int it = 0; it < 3; it++) {                                         \
            int ci = tid + it * 256;                                             \
            const char* g; uint32_t dd;                                          \
            if (ci < 256) {                                                      \
                int row = ci >> 2, cc = ci & 3;                                   \
                g = (const char*)(srcA + (size_t)row * D_ + (k0)) + cc * 16;      \
                dd = sb + (uint32_t)((s) * STGB + row * ROWB + cc * 16);          \
            } else {                                                              \
                int u = ci - 256;                                                 \
                int row = u >> 2, cc = u & 3;                                     \
                g = (const char*)(srcB + (size_t)row * D_ + (k0)) + cc * 16;      \
                dd = sb + (uint32_t)((s) * STGB + TA + row * ROWB + cc * 16);     \
            }                                                                     \
            cpasync16(dd, g);                                                     \
        }                                                                         \
        CP_COMMIT();                                                              \
    } while (0)

    LOAD_STAGE(0, 0);

    for (int ks = 0; ks < NSTAGE; ks++) {
        int s = ks & 1;
        if (ks + 1 < NSTAGE) { LOAD_STAGE(s ^ 1, (ks + 1) * BK); CP_WAIT(1); }
        else                 { CP_WAIT(0); }
        __syncthreads();

        uint32_t bAh = sb + (uint32_t)(s * STGB);
        uint32_t bBh = bAh + TA;

        #pragma unroll
        for (int k16 = 0; k16 < 2; k16++) {
            uint32_t kb = (uint32_t)(k16 * 32);
            uint32_t ah[2][4];
            uint32_t bhf[4][2];
            #pragma unroll
            for (int mt = 0; mt < 2; mt++)
                ldsm4(ah[mt], bAh + (uint32_t)(mt * 16 * ROWB) + kb + aoff);
            #pragma unroll
            for (int np = 0; np < 2; np++) {
                uint32_t t4[4];
                ldsm4(t4, bBh + (uint32_t)(np * 16 * ROWB) + kb + boff);
                bhf[np*2+0][0] = t4[0]; bhf[np*2+0][1] = t4[2];
                bhf[np*2+1][0] = t4[1]; bhf[np*2+1][1] = t4[3];
            }
            #pragma unroll
            for (int mt = 0; mt < 2; mt++)
                #pragma unroll
                for (int nt = 0; nt < 4; nt++)
                    mma16816(acc[mt][nt], ah[mt], &bhf[nt][0], &bhf[nt][1]);
        }
        __syncthreads();
    }

    int g = lane >> 2, tq = lane & 3;
    #pragma unroll
    for (int mt = 0; mt < 2; mt++) {
        int m0 = mblk * BM + wr * 32 + mt * 16 + g;
        #pragma unroll
        for (int nt = 0; nt < 4; nt++) {
            int n = nblk * BN + wc * 32 + nt * 8 + tq * 2;
            if (m0 < act)
                *reinterpret_cast<float2*>(d_S + (size_t)m0 * N_ + n) =
                    make_float2(acc[mt][nt][0], acc[mt][nt][1]);
            if (m0 + 8 < act)
                *reinterpret_cast<float2*>(d_S + (size_t)(m0 + 8) * N_ + n) =
                    make_float2(acc[mt][nt][2], acc[mt][nt][3]);
        }
    }
}

// ============================================================
// post2: fused G-reduce + norms + softmax + symmetric quad form.
// ============================================================
__global__ void __launch_bounds__(256, 3) post2_kernel(const int* __restrict__ cap_lens,
                                                       float* __restrict__ out) {
    extern __shared__ float dyn[];
    float* Gs  = dyn + P2_GS;            // [36][36]
    float* Ss  = dyn + P2_SS;            // [8][32][37] flat
    float* rcn = dyn + P2_RCN;           // [64][38]
    __shared__ int cl[C_], offs[C_ + 1];

    int i = blockIdx.x;
    int tid = threadIdx.x, wid = tid >> 5, lane = tid & 31;

    compute_offs(cap_lens, cl, offs, tid);
    int act = offs[C_];
    int base0 = blockIdx.y * 256;
    if (base0 >= act) return;

    // reduce gram partials while loading G
    for (int idx = tid; idx < R_ * R_; idx += 256) {
        float s = 0.f;
        #pragma unroll
        for (int p = 0; p < GCH; p++) s += d_Gp[p][i * (R_*R_) + idx];
        Gs[idx] = s;
    }

    int blk_rows = act - base0;
    if (blk_rows > 256) blk_rows = 256;

    // stage S rows (warp per 32 rows)
    {
        int m0w = base0 + wid * 32;
        int nrows = act - m0w;
        if (nrows > 32) nrows = 32;
        if (nrows < 0) nrows = 0;
        for (int idx = lane; idx < nrows * R_; idx += 32) {
            int row = idx / R_, r = idx - row * R_;
            Ss[(wid * 32 + row) * 37 + r] = d_S[(size_t)(m0w + row) * N_ + i * R_ + r];
        }
    }
    __syncthreads();

    // fused norms
    int c_lo = find_c(offs, base0);
    int c_hi = find_c(offs, base0 + blk_rows - 1);
    int ncs = c_hi - c_lo + 1;           // <= 64
    for (int item = tid; item < ncs * R_; item += 256) {
        int ci = item / R_, r = item - ci * R_;
        int c = c_lo + ci;
        int o = offs[c], nw2 = offs[c + 1] - o;
        float s = 0.f;
        for (int w = 0; w < nw2; w++) {
            int row = o + w;
            int lr2 = row - base0;
            float v = (lr2 >= 0 && lr2 < 256) ? Ss[lr2 * 37 + r]
                                              : d_S[(size_t)row * N_ + i * R_ + r];
            v = (v >= 0.f) ? v : 0.1f * v;
            s = fmaf(v, v, s);
        }
        rcn[ci * 38 + r] = SMOOTH_ / (sqrtf(s) + EPS_);
    }
    __syncthreads();

    int myrow = base0 + wid * 32 + lane;
    if (myrow < act && (wid * 32 + lane) < blk_rows) {
        int c = find_c(offs, myrow);
        int w = myrow - offs[c];
        const float* rc = rcn + (c - c_lo) * 38;
        const float* sr = Ss + (wid * 32 + lane) * 37;

        float a[R_];
        float sum0 = 0.f, sum1 = 0.f, sum2 = 0.f, sum3 = 0.f;
        float sd0 = 0.f, sd1 = 0.f, sd2 = 0.f, sd3 = 0.f;
        #pragma unroll
        for (int r = 0; r < R_; r += 4) {
            float v0 = sr[r+0], v1 = sr[r+1];
            float v2 = sr[r+2], v3 = sr[r+3];
            float l0 = (v0 >= 0.f) ? v0 : 0.1f * v0;
            float l1 = (v1 >= 0.f) ? v1 : 0.1f * v1;
            float l2 = (v2 >= 0.f) ? v2 : 0.1f * v2;
            float l3 = (v3 >= 0.f) ? v3 : 0.1f * v3;
            float e0 = __expf(l0 * rc[r+0]);
            float e1 = __expf(l1 * rc[r+1]);
            float e2 = __expf(l2 * rc[r+2]);
            float e3 = __expf(l3 * rc[r+3]);
            a[r+0] = e0; a[r+1] = e1; a[r+2] = e2; a[r+3] = e3;
            sum0 += e0; sum1 += e1; sum2 += e2; sum3 += e3;
            sd0 = fmaf(e0, v0, sd0); sd1 = fmaf(e1, v1, sd1);
            sd2 = fmaf(e2, v2, sd2); sd3 = fmaf(e3, v3, sd3);
        }
        float sum = (sum0 + sum1) + (sum2 + sum3);
        float sd  = (sd0 + sd1) + (sd2 + sd3);
        float inv = 1.f / sum;

        float qd = 0.f, qo0 = 0.f, qo1 = 0.f;
        #pragma unroll
        for (int rg = 0; rg < 9; rg++) {
            #pragma unroll
            for (int aa = 0; aa < 4; aa++) {
                float4 g4 = *reinterpret_cast<const float4*>(&Gs[(4*rg+aa) * R_ + 4*rg]);
                float t = g4.x * a[4*rg+0];
                t = fmaf(g4.y, a[4*rg+1], t);
                t = fmaf(g4.z, a[4*rg+2], t);
                t = fmaf(g4.w, a[4*rg+3], t);
                qd = fmaf(a[4*rg+aa], t, qd);
            }
            #pragma unroll
            for (int cg = rg + 1; cg < 9; cg++) {
                #pragma unroll
                for (int aa = 0; aa < 4; aa++) {
                    float4 g4 = *reinterpret_cast<const float4*>(&Gs[(4*rg+aa) * R_ + 4*cg]);
                    float t = g4.x * a[4*cg+0];
                    t = fmaf(g4.y, a[4*cg+1], t);
                    t = fmaf(g4.z, a[4*cg+2], t);
                    t = fmaf(g4.w, a[4*cg+3], t);
                    if ((cg ^ rg) & 1) qo0 = fmaf(a[4*rg+aa], t, qo0);
                    else               qo1 = fmaf(a[4*rg+aa], t, qo1);
                }
            }
        }
        float qe = qd + 2.f * (qo0 + qo1);

        float n = sqrtf(qe) * inv;
        float dot = sd * inv;
        float denom = n + EPS_;
        float w12 = dot / denom;
        float w2v = n / denom;
        float w1v = sqrtf(d_capn[c * W_ + w]);
        float sim = w12 / fmaxf(w1v * w2v, EPS_);
        out[((size_t)i * C_ + c) * W_ + w] = sim;
    }
}

// ============================================================
extern "C" void kernel_launch(void* const* d_in, const int* in_sizes, int n_in,
                              void* d_out, int out_size) {
    const float* imgs     = (const float*)d_in[0];
    const float* caps     = (const float*)d_in[1];
    const int*   cap_lens = (const int*)d_in[3];
    float* out = (float*)d_out;

    cudaFuncSetAttribute(gemm_mma_kernel, cudaFuncAttributeMaxDynamicSharedMemorySize, GEMM_SMEM);
    cudaFuncSetAttribute(post2_kernel, cudaFuncAttributeMaxDynamicSharedMemorySize, POST2_SMEM);

    mega_kernel<<<MEGAB, 256>>>(caps, imgs, cap_lens, out);
    gemm_mma_kernel<<<GEMMB + GRAMB, 256, GEMM_SMEM>>>(imgs);
    dim3 pgrid(I_, 8);
    post2_kernel<<<pgrid, 256, POST2_SMEM>>>(cap_lens, out);
}